// round 12
// baseline (speedup 1.0000x reference)
#include <cuda_runtime.h>
#include <cuda_fp16.h>
#include <math.h>
#include <stdint.h>

#define BATCH 8
#define DIMC  512
#define HW    4096
#define GH    64     // BATCH*HEADS
#define DH    64

// ---------------- scratch (device globals; allocation-free) ----------------
__device__ __align__(128) __half g_qh [BATCH * DIMC * HW];     // q proj fp16 [b][m][p]
__device__ __align__(128) __half g_kk [BATCH * DIMC * HW];     // k proj fp16 [b][m][p]
__device__ __align__(128) __half g_ctxh[BATCH * DIMC * HW];    // normalized ctx fp16
__device__ __align__(128) __half g_qsh [BATCH * DIMC * HW];    // normalized qs fp16 (residual)
__device__ __align__(128) __half g_aoh [BATCH * DIMC * HW];    // attention out fp16
__device__ __align__(128) __half g_wq [512 * 512];
__device__ __align__(128) __half g_wkv[1024 * 512];
__device__ __align__(128) __half g_wo [512 * 512];
__device__ float g_qinv[GH * HW];
__device__ float g_kinv[GH * HW];
__device__ float g_qprobe[GH * DH];
__device__ float g_kh[GH * DH * 64];
__device__ float g_kw[GH * DH * 64];
__device__ int   g_idxh[GH * 8];
__device__ int   g_idxw[GH * 8];
__device__ __half g_kT[GH * 64 * 64];   // [bh][d][j]
__device__ __half g_vf[GH * 64 * 64];   // [bh][j][d]

// ================= warp-MMA helpers =================
__device__ __forceinline__ uint32_t smem_u32(const void* p) {
    uint32_t a;
    asm("{ .reg .u64 t; cvta.to.shared.u64 t, %1; cvt.u32.u64 %0, t; }" : "=r"(a) : "l"(p));
    return a;
}
__device__ __forceinline__ void cp16(uint32_t d, const void* s) {
    asm volatile("cp.async.cg.shared.global [%0], [%1], 16;" :: "r"(d), "l"(s));
}
__device__ __forceinline__ void ldsm4(uint32_t* r, uint32_t a) {
    asm volatile("ldmatrix.sync.aligned.m8n8.x4.shared.b16 {%0,%1,%2,%3}, [%4];"
                 : "=r"(r[0]), "=r"(r[1]), "=r"(r[2]), "=r"(r[3]) : "r"(a));
}
__device__ __forceinline__ void ldsm4t(uint32_t* r, uint32_t a) {
    asm volatile("ldmatrix.sync.aligned.m8n8.x4.trans.shared.b16 {%0,%1,%2,%3}, [%4];"
                 : "=r"(r[0]), "=r"(r[1]), "=r"(r[2]), "=r"(r[3]) : "r"(a));
}
__device__ __forceinline__ void mma16816(float* c, const uint32_t* a, const uint32_t* b) {
    asm volatile(
        "mma.sync.aligned.m16n8k16.row.col.f32.f16.f16.f32 "
        "{%0,%1,%2,%3}, {%4,%5,%6,%7}, {%8,%9}, {%0,%1,%2,%3};"
        : "+f"(c[0]), "+f"(c[1]), "+f"(c[2]), "+f"(c[3])
        : "r"(a[0]), "r"(a[1]), "r"(a[2]), "r"(a[3]), "r"(b[0]), "r"(b[1]));
}

#define A_PAD 72
#define B_PAD 136
#define A_PL  (128 * A_PAD)
#define ST_ELEMS (A_PL + 64 * B_PAD)
#define GEMM_SMEM (3 * ST_ELEMS * 2)

// shared GEMM mainloop body: fills acc[2][8][4] for this warp.
// B-fragments double-buffered: ldsm for kk+1 issued before MMAs of kk.
#define GEMM_MAINLOOP(copy_chunk)                                                        \
    copy_chunk(0);                                                                       \
    copy_chunk(1);                                                                       \
    for (int c = 0; c < 8; c++) {                                                        \
        if (c < 7) { asm volatile("cp.async.wait_group 1;" ::: "memory"); }              \
        else       { asm volatile("cp.async.wait_group 0;" ::: "memory"); }              \
        __syncthreads();                                                                 \
        if (c < 6) copy_chunk(c + 2);                                                    \
        uint32_t sb = sbase + (uint32_t)(c % 3) * (ST_ELEMS * 2);                        \
        uint32_t a_0 = sb + (uint32_t)((wm + (lane & 15)) * A_PAD + (lane >> 4) * 8) * 2;\
        uint32_t b_0 = sb + (uint32_t)(A_PL + (lane & 15) * B_PAD + wn                   \
                                       + (lane >> 4) * 8) * 2;                           \
        uint32_t bfr[2][4][4];                                                           \
        _Pragma("unroll")                                                                \
        for (int nt2 = 0; nt2 < 4; nt2++)                                                \
            ldsm4t(bfr[0][nt2], b_0 + (uint32_t)(nt2 * 16) * 2);                         \
        _Pragma("unroll")                                                                \
        for (int kk = 0; kk < 4; kk++) {                                                 \
            uint32_t ah[2][4];                                                           \
            _Pragma("unroll")                                                            \
            for (int mb = 0; mb < 2; mb++)                                               \
                ldsm4(ah[mb], a_0 + (uint32_t)(mb * 16 * A_PAD + kk * 16) * 2);          \
            if (kk < 3) {                                                                \
                _Pragma("unroll")                                                        \
                for (int nt2 = 0; nt2 < 4; nt2++)                                        \
                    ldsm4t(bfr[(kk + 1) & 1][nt2],                                       \
                           b_0 + (uint32_t)((kk + 1) * 16 * B_PAD + nt2 * 16) * 2);      \
            }                                                                            \
            const uint32_t (*bc)[4] = bfr[kk & 1];                                       \
            _Pragma("unroll")                                                            \
            for (int mb = 0; mb < 2; mb++)                                               \
                _Pragma("unroll")                                                        \
                for (int nb = 0; nb < 8; nb++)                                           \
                    mma16816(acc[mb][nb], ah[mb], &bc[nb >> 1][(nb & 1) * 2]);           \
        }                                                                                \
    }

// ======== merged q+k projection GEMM: z<8 -> k, z>=8 -> q; fp16 out, M=512 ========
__global__ void __launch_bounds__(256, 2)
proj_gemm_kernel(const __half* __restrict__ Wk, const __half* __restrict__ Xk,
                 __half* __restrict__ Yk,
                 const __half* __restrict__ Wq, const __half* __restrict__ Xq,
                 __half* __restrict__ Yq) {
    extern __shared__ __half sm[];
    uint32_t sbase = smem_u32(sm);
    int tid = threadIdx.x;
    int lane = tid & 31, wid = tid >> 5;
    int z = blockIdx.z;
    const __half *W, *X;
    __half* Yh;
    int b;
    if (z < 8) { W = Wk; X = Xk; Yh = Yk; b = z; }
    else       { W = Wq; X = Xq; Yh = Yq; b = z - 8; }
    int m0 = blockIdx.y * 128, n0 = blockIdx.x * 128;
    const __half* wsrc = W + (size_t)m0 * 512;
    const __half* xsrc = X + (size_t)b * DIMC * HW + n0;

    auto copy_chunk = [&](int c) {
        uint32_t sb = sbase + (uint32_t)(c % 3) * (ST_ELEMS * 2);
#pragma unroll
        for (int i = 0; i < 4; i++) {
            int t = tid + i * 256;
            int m = t >> 3, j = t & 7;
            cp16(sb + (uint32_t)(m * A_PAD + j * 8) * 2,
                 wsrc + (size_t)m * 512 + c * 64 + j * 8);
        }
#pragma unroll
        for (int i = 0; i < 4; i++) {
            int t = tid + i * 256;
            int k = t >> 4, j = t & 15;
            cp16(sb + (uint32_t)(A_PL + k * B_PAD + j * 8) * 2,
                 xsrc + (size_t)(c * 64 + k) * HW + j * 8);
        }
        asm volatile("cp.async.commit_group;" ::: "memory");
    };

    float acc[2][8][4] = {};
    int wm = (wid & 3) * 32;
    int wn = (wid >> 2) * 64;

    GEMM_MAINLOOP(copy_chunk)

    int g = lane >> 2, tig = lane & 3;
#pragma unroll
    for (int mb = 0; mb < 2; mb++) {
#pragma unroll
        for (int nb = 0; nb < 8; nb++) {
            int m = m0 + wm + mb * 16 + g;
            int n = n0 + wn + nb * 8 + tig * 2;
            size_t off0 = ((size_t)b * 512 + m) * HW + n;
            size_t off1 = off0 + (size_t)8 * HW;
            float* p = acc[mb][nb];
            *(__half2*)(Yh + off0) = __floats2half2_rn(p[0], p[1]);
            *(__half2*)(Yh + off1) = __floats2half2_rn(p[2], p[3]);
        }
    }
}

// ======== out-proj GEMM: Y = gamma*(W@X) + addend(fp16), fp32 out, M=512 ========
__global__ void __launch_bounds__(256, 2)
out_gemm_kernel(const __half* __restrict__ W, const __half* __restrict__ X,
                float* __restrict__ Y, const float* __restrict__ gammap,
                const __half* __restrict__ addend) {
    extern __shared__ __half sm[];
    uint32_t sbase = smem_u32(sm);
    int tid = threadIdx.x;
    int lane = tid & 31, wid = tid >> 5;
    int b = blockIdx.z;
    int m0 = blockIdx.y * 128, n0 = blockIdx.x * 128;
    const __half* wsrc = W + (size_t)m0 * 512;
    const __half* xsrc = X + (size_t)b * DIMC * HW + n0;

    auto copy_chunk = [&](int c) {
        uint32_t sb = sbase + (uint32_t)(c % 3) * (ST_ELEMS * 2);
#pragma unroll
        for (int i = 0; i < 4; i++) {
            int t = tid + i * 256;
            int m = t >> 3, j = t & 7;
            cp16(sb + (uint32_t)(m * A_PAD + j * 8) * 2,
                 wsrc + (size_t)m * 512 + c * 64 + j * 8);
        }
#pragma unroll
        for (int i = 0; i < 4; i++) {
            int t = tid + i * 256;
            int k = t >> 4, j = t & 15;
            cp16(sb + (uint32_t)(A_PL + k * B_PAD + j * 8) * 2,
                 xsrc + (size_t)(c * 64 + k) * HW + j * 8);
        }
        asm volatile("cp.async.commit_group;" ::: "memory");
    };

    float acc[2][8][4] = {};
    int wm = (wid & 3) * 32;
    int wn = (wid >> 2) * 64;

    GEMM_MAINLOOP(copy_chunk)

    float ga = gammap[0];
    int g = lane >> 2, tig = lane & 3;
#pragma unroll
    for (int mb = 0; mb < 2; mb++) {
#pragma unroll
        for (int nb = 0; nb < 8; nb++) {
            int m = m0 + wm + mb * 16 + g;
            int n = n0 + wn + nb * 8 + tig * 2;
            size_t off0 = ((size_t)b * 512 + m) * HW + n;
            size_t off1 = off0 + (size_t)8 * HW;
            float* p = acc[mb][nb];
            float2 d0 = __half22float2(*(const __half2*)(addend + off0));
            float2 d1 = __half22float2(*(const __half2*)(addend + off1));
            *(float2*)(Y + off0) = make_float2(ga * p[0] + d0.x, ga * p[1] + d0.y);
            *(float2*)(Y + off1) = make_float2(ga * p[2] + d1.x, ga * p[3] + d1.y);
        }
    }
}

// ======== v-gather GEMM + k-gather: per bh ========
#define VG_APAD 520
#define VG_BOFF (64 * VG_APAD)
#define VG_SMEM ((VG_BOFF + 512 * 72) * 2)
__global__ void __launch_bounds__(128) vgather_kernel() {
    extern __shared__ __half sm[];
    __shared__ int sidx[16];
    uint32_t sbase = smem_u32(sm);
    int tid = threadIdx.x, lane = tid & 31, w = tid >> 5;
    int bh = blockIdx.x;

    if (tid < 8) sidx[tid] = g_idxh[bh * 8 + tid];
    else if (tid < 16) sidx[tid] = g_idxw[bh * 8 + tid - 8];

    // A: wv rows for this head
    const __half* wv = g_wkv + (size_t)(512 + (bh & 7) * 64) * 512;
#pragma unroll
    for (int i = 0; i < 32; i++) {
        int t = tid + i * 128;
        int row = t >> 6, j8 = t & 63;
        cp16(sbase + (uint32_t)(row * VG_APAD + j8 * 8) * 2, wv + row * 512 + j8 * 8);
    }
    asm volatile("cp.async.commit_group;" ::: "memory");
    __syncthreads();                    // sidx visible

    int pj = sidx[(tid & 63) >> 3] * 64 + sidx[8 + (tid & 7)];   // position for j = tid&63

    // kT gather: [d][j], d = t>>6, j = t&63 (same pj per j)
    {
        const __half* kk = g_kk + (size_t)bh * 64 * HW;
        const float kiv = g_kinv[bh * HW + pj];
#pragma unroll 8
        for (int i = 0; i < 32; i++) {
            int t = tid + i * 128;
            int d = t >> 6, j = t & 63;
            float k = __half2float(kk[(size_t)d * HW + pj]) * kiv;
            g_kT[bh * 4096 + d * 64 + j] = __float2half_rn(k);
        }
    }

    // B: gathered ctx [512 c][64 j]
    const __half* ctx = g_ctxh + (size_t)(bh >> 3) * DIMC * HW;
#pragma unroll 8
    for (int i = 0; i < 256; i++) {
        int t = tid + i * 128;
        int k = t >> 6, j = t & 63;
        sm[VG_BOFF + k * 72 + j] = ctx[(size_t)k * HW + pj];
    }
    asm volatile("cp.async.wait_group 0;" ::: "memory");
    __syncthreads();

    float acc[8][4] = {};
    uint32_t a_0 = sbase + (uint32_t)((w * 16 + (lane & 15)) * VG_APAD + (lane >> 4) * 8) * 2;
    uint32_t b_0 = sbase + (uint32_t)(VG_BOFF + (lane & 15) * 72 + (lane >> 4) * 8) * 2;
#pragma unroll 4
    for (int kc = 0; kc < 32; kc++) {
        uint32_t af[4], bf[4][4];
        ldsm4(af, a_0 + (uint32_t)(kc * 16) * 2);
#pragma unroll
        for (int nt2 = 0; nt2 < 4; nt2++)
            ldsm4t(bf[nt2], b_0 + (uint32_t)(kc * 16 * 72 + nt2 * 16) * 2);
#pragma unroll
        for (int nb = 0; nb < 8; nb++)
            mma16816(acc[nb], af, &bf[nb >> 1][(nb & 1) * 2]);
    }

    __half* dst = g_vf + bh * 4096;
    int g = lane >> 2, tig = lane & 3;
    int d0 = w * 16 + g;
#pragma unroll
    for (int nb = 0; nb < 8; nb++) {
        int j0 = nb * 8 + tig * 2;
        float* p = acc[nb];
        dst[j0 * 64 + d0]           = __float2half_rn(p[0]);
        dst[(j0 + 1) * 64 + d0]     = __float2half_rn(p[1]);
        dst[j0 * 64 + d0 + 8]       = __float2half_rn(p[2]);
        dst[(j0 + 1) * 64 + d0 + 8] = __float2half_rn(p[3]);
    }
}

// ---------------- fused channel layernorm (both tensors, one launch) ----------------
__global__ __launch_bounds__(256) void fused_norm_kernel(const float* __restrict__ in0,
                                                         const float* __restrict__ gw0,
                                                         const float* __restrict__ bw0,
                                                         __half* __restrict__ oh0,
                                                         const float* __restrict__ in1,
                                                         const float* __restrict__ gw1,
                                                         const float* __restrict__ bw1,
                                                         __half* __restrict__ oh1) {
    __shared__ float shs[8][32], shq[8][32];
    __shared__ float smean[32], srstd[32];
    int half2nd = blockIdx.x >> 10;
    const float* in = half2nd ? in1 : in0;
    const float* gw = half2nd ? gw1 : gw0;
    const float* bw = half2nd ? bw1 : bw0;
    __half* oh = half2nd ? oh1 : oh0;
    int tid = threadIdx.x;
    int px = tid & 31, cg = tid >> 5;
    int pos = (blockIdx.x & 1023) * 32 + px;
    int b = pos >> 12, sp = pos & 4095;
    size_t base = (size_t)b * DIMC * HW + sp;
    int c0 = cg * 64;
    float v[64];
    float s = 0.f, q = 0.f;
#pragma unroll 8
    for (int c = 0; c < 64; c++) {
        float x = in[base + (size_t)(c0 + c) * HW];
        v[c] = x; s += x; q += x * x;
    }
    shs[cg][px] = s; shq[cg][px] = q;
    __syncthreads();
    if (cg == 0) {
        float ts = 0.f, tq = 0.f;
#pragma unroll
        for (int g = 0; g < 8; g++) { ts += shs[g][px]; tq += shq[g][px]; }
        float mean = ts * (1.0f / 512.0f);
        float var = tq * (1.0f / 512.0f) - mean * mean;
        smean[px] = mean;
        srstd[px] = rsqrtf(var + 1e-5f);
    }
    __syncthreads();
    float m = smean[px], r = srstd[px];
#pragma unroll 8
    for (int c = 0; c < 64; c++) {
        float y = (v[c] - m) * r * gw[c0 + c] + bw[c0 + c];
        oh[base + (size_t)(c0 + c) * HW] = __float2half_rn(y);
    }
}

// ---------------- all weights fp32 -> fp16, one launch ----------------
__global__ __launch_bounds__(256) void wconv_kernel(const float* __restrict__ wq,
                                                    const float* __restrict__ wkv,
                                                    const float* __restrict__ wo) {
    int i4 = (blockIdx.x * 256 + threadIdx.x) * 4;
    const float* src;
    __half* dst;
    int off;
    if (i4 < 262144)       { src = wq;  dst = g_wq;  off = i4; }
    else if (i4 < 786432)  { src = wkv; dst = g_wkv; off = i4 - 262144; }
    else                   { src = wo;  dst = g_wo;  off = i4 - 786432; }
    float4 x = *(const float4*)(src + off);
    *(__half2*)(dst + off)     = __floats2half2_rn(x.x, x.y);
    *(__half2*)(dst + off + 2) = __floats2half2_rn(x.z, x.w);
}

// ---------------- inverse L2 norms for q and k, one launch ----------------
__global__ __launch_bounds__(256) void inv_norm_kernel() {
    int gidx = blockIdx.x * 256 + threadIdx.x;
    int qk = gidx >> 18;
    int idx = gidx & 262143;
    const __half* t = qk ? g_kk : g_qh;
    size_t base = (size_t)(idx >> 12) * (64 * HW) + (idx & 4095);
    float ss = 0.f;
#pragma unroll 8
    for (int d = 0; d < 64; d++) {
        float x = __half2float(t[base + (size_t)d * HW]);
        ss += x * x;
    }
    float r = 1.0f / fmaxf(sqrtf(ss), 1e-12f);
    if (qk == 0) g_qinv[idx] = r; else g_kinv[idx] = r;
}

// ---------------- merged stats: khw (blocks 0..4095) + qprobe (4096..8191) ----------------
__global__ __launch_bounds__(256) void stats_kernel() {
    __shared__ float pl[4096];
    int tid = threadIdx.x;
    if (blockIdx.x < 4096) {
        int bh = blockIdx.x >> 6, c = blockIdx.x & 63;
        size_t base = ((size_t)bh * 64 + c) * HW;
        const float* ki = g_kinv + bh * HW;
        for (int i = tid; i < 2048; i += 256) {
            __half2 h = *(const __half2*)(g_kk + base + 2 * i);
            float2 kv2 = __half22float2(h);
            float2 ki2 = *(const float2*)(ki + 2 * i);
            pl[2 * i]     = fabsf(kv2.x) * ki2.x;
            pl[2 * i + 1] = fabsf(kv2.y) * ki2.y;
        }
        __syncthreads();
        if (tid < 64) {
            int h = tid;
            float s = 0.f;
#pragma unroll 8
            for (int w = 0; w < 64; w++) s += pl[h * 64 + ((w + h) & 63)];
            g_kh[bh * 4096 + c * 64 + h] = s;
        } else if (tid < 128) {
            int w = tid - 64;
            float s = 0.f;
#pragma unroll 8
            for (int h = 0; h < 64; h++) s += pl[h * 64 + w];
            g_kw[bh * 4096 + c * 64 + w] = s;
        }
    } else {
        int bid = blockIdx.x - 4096;
        int g = bid >> 6;
        const __half2* p2 = (const __half2*)(g_qh + (size_t)bid * HW);
        const float2* iv2 = (const float2*)(g_qinv + (size_t)g * HW);
        float s = 0.f;
        for (int i = tid; i < 2048; i += 256) {
            float2 v = __half22float2(p2[i]);
            float2 iv = iv2[i];
            s += fabsf(v.x) * iv.x + fabsf(v.y) * iv.y;
        }
        pl[tid] = s;
        __syncthreads();
        for (int st = 128; st > 0; st >>= 1) {
            if (tid < st) pl[tid] += pl[tid + st];
            __syncthreads();
        }
        if (tid == 0) g_qprobe[bid] = pl[0];
    }
}

// ---------------- scores + top-8 selection ----------------
__global__ __launch_bounds__(64) void score_topk_kernel() {
    int bh = blockIdx.x;
    int h = threadIdx.x;
    __shared__ float sr[64], sc[64];
    float a = 0.f, bb = 0.f;
    for (int c = 0; c < 64; c++) {
        float qp = g_qprobe[bh * 64 + c];
        a  += qp * g_kh[bh * 4096 + c * 64 + h];
        bb += qp * g_kw[bh * 4096 + c * 64 + h];
    }
    sr[h] = a; sc[h] = bb;
    __syncthreads();
    if (h == 0) {
        for (int i = 0; i < 8; i++) {
            float best = -INFINITY; int bi = 0;
            for (int j = 0; j < 64; j++) if (sr[j] > best) { best = sr[j]; bi = j; }
            g_idxh[bh * 8 + i] = bi;
            sr[bi] = -INFINITY;
        }
    } else if (h == 1) {
        for (int i = 0; i < 8; i++) {
            float best = -INFINITY; int bi = 0;
            for (int j = 0; j < 64; j++) if (sc[j] > best) { best = sc[j]; bi = j; }
            g_idxw[bh * 8 + i] = bi;
            sc[bi] = -INFINITY;
        }
    }
}

// ---------------- MMA attention: per (bh, 128-query tile) ----------------
__global__ __launch_bounds__(128) void attn_kernel() {
    __shared__ __half sQ[128 * A_PAD];
    __shared__ __half sK[64 * A_PAD];
    __shared__ __half sV[64 * A_PAD];
    int tid = threadIdx.x, lane = tid & 31, w = tid >> 5;
    int p0 = blockIdx.x * 128, bh = blockIdx.y;
    uint32_t sQa = smem_u32(sQ), sKa = smem_u32(sK), sVa = smem_u32(sV);

    const __half* kt = g_kT + bh * 4096;
    const __half* vf = g_vf + bh * 4096;
#pragma unroll
    for (int i = 0; i < 4; i++) {
        int t = tid + i * 128;
        int r = t >> 3, j = t & 7;
        cp16(sKa + (uint32_t)(r * A_PAD + j * 8) * 2, kt + r * 64 + j * 8);
        cp16(sVa + (uint32_t)(r * A_PAD + j * 8) * 2, vf + r * 64 + j * 8);
    }
    asm volatile("cp.async.commit_group;" ::: "memory");

    const __half* qp = g_qh + (size_t)bh * 64 * HW + p0;
    const float* qi = g_qinv + bh * HW + p0;
#pragma unroll
    for (int i = 0; i < 32; i++) {
        int t = tid + i * 128;
        int d2 = t >> 7, p = t & 127;
        float iv = qi[p];
        __half2 h = __floats2half2_rn(__half2float(qp[(size_t)(2 * d2) * HW + p]) * iv,
                                      __half2float(qp[(size_t)(2 * d2 + 1) * HW + p]) * iv);
        *(__half2*)(sQ + p * A_PAD + 2 * d2) = h;
    }
    asm volatile("cp.async.wait_group 0;" ::: "memory");
    __syncthreads();

    float sacc[2][8][4] = {};
#pragma unroll
    for (int kk = 0; kk < 4; kk++) {
        uint32_t a[2][4], bk[4][4];
#pragma unroll
        for (int mb = 0; mb < 2; mb++)
            ldsm4(a[mb], sQa + (uint32_t)((w * 32 + mb * 16 + (lane & 15)) * A_PAD
                                          + kk * 16 + (lane >> 4) * 8) * 2);
#pragma unroll
        for (int nt2 = 0; nt2 < 4; nt2++)
            ldsm4t(bk[nt2], sKa + (uint32_t)((kk * 16 + (lane & 15)) * A_PAD
                                             + nt2 * 16 + (lane >> 4) * 8) * 2);
#pragma unroll
        for (int mb = 0; mb < 2; mb++)
#pragma unroll
            for (int nt = 0; nt < 8; nt++)
                mma16816(sacc[mb][nt], a[mb], &bk[nt >> 1][(nt & 1) * 2]);
    }

    float is0[2], is1[2];
#pragma unroll
    for (int mb = 0; mb < 2; mb++) {
        float mx0 = -INFINITY, mx1 = -INFINITY;
#pragma unroll
        for (int nt = 0; nt < 8; nt++) {
            mx0 = fmaxf(mx0, fmaxf(sacc[mb][nt][0], sacc[mb][nt][1]));
            mx1 = fmaxf(mx1, fmaxf(sacc[mb][nt][2], sacc[mb][nt][3]));
        }
        mx0 = fmaxf(mx0, __shfl_xor_sync(0xffffffff, mx0, 1));
        mx0 = fmaxf(mx0, __shfl_xor_sync(0xffffffff, mx0, 2));
        mx1 = fmaxf(mx1, __shfl_xor_sync(0xffffffff, mx1, 1));
        mx1 = fmaxf(mx1, __shfl_xor_sync(0xffffffff, mx1, 2));
        float s0 = 0.f, s1 = 0.f;
#pragma unroll
        for (int nt = 0; nt < 8; nt++) {
            sacc[mb][nt][0] = expf(sacc[mb][nt][0] - mx0);
            sacc[mb][nt][1] = expf(sacc[mb][nt][1] - mx0);
            sacc[mb][nt][2] = expf(sacc[mb][nt][2] - mx1);
            sacc[mb][nt][3] = expf(sacc[mb][nt][3] - mx1);
            s0 += sacc[mb][nt][0] + sacc[mb][nt][1];
            s1 += sacc[mb][nt][2] + sacc[mb][nt][3];
        }
        s0 += __shfl_xor_sync(0xffffffff, s0, 1);
        s0 += __shfl_xor_sync(0xffffffff, s0, 2);
        s1 += __shfl_xor_sync(0xffffffff, s1, 1);
        s1 += __shfl_xor_sync(0xffffffff, s1, 2);
        is0[mb] = 1.0f / s0;
        is1[mb] = 1.0f / s1;
    }

    uint32_t pa[2][4][4];
#pragma unroll
    for (int mb = 0; mb < 2; mb++)
#pragma unroll
        for (int u = 0; u < 4; u++) {
            __half2 h0 = __floats2half2_rn(sacc[mb][2*u][0],   sacc[mb][2*u][1]);
            __half2 h1 = __floats2half2_rn(sacc[mb][2*u][2],   sacc[mb][2*u][3]);
            __half2 h2 = __floats2half2_rn(sacc[mb][2*u+1][0], sacc[mb][2*u+1][1]);
            __half2 h3 = __floats2half2_rn(sacc[mb][2*u+1][2], sacc[mb][2*u+1][3]);
            pa[mb][u][0] = *(uint32_t*)&h0;
            pa[mb][u][1] = *(uint32_t*)&h1;
            pa[mb][u][2] = *(uint32_t*)&h2;
            pa[mb][u][3] = *(uint32_t*)&h3;
        }

    float oacc[2][8][4] = {};
#pragma unroll
    for (int u = 0; u < 4; u++) {
        uint32_t bv[4][4];
#pragma unroll
        for (int nt2 = 0; nt2 < 4; nt2++)
            ldsm4t(bv[nt2], sVa + (uint32_t)((u * 16 + (lane & 15)) * A_PAD
                                             + nt2 * 16 + (lane >> 4) * 8) * 2);
#pragma unroll
        for (int mb = 0; mb < 2; mb++)
#pragma unroll
            for (int nt = 0; nt < 8; nt++)
                mma16816(oacc[mb][nt], pa[mb][u], &bv[nt >> 1][(nt & 1) * 2]);
    }

    __syncthreads();
#pragma unroll
    for (int mb = 0; mb < 2; mb++) {
        int q = w * 32 + mb * 16 + (lane >> 2);
#pragma unroll
        for (int nt = 0; nt < 8; nt++) {
            int d = nt * 8 + (lane & 3) * 2;
            __half2 h0 = __floats2half2_rn(oacc[mb][nt][0] * is0[mb],
                                           oacc[mb][nt][1] * is0[mb]);
            __half2 h1 = __floats2half2_rn(oacc[mb][nt][2] * is1[mb],
                                           oacc[mb][nt][3] * is1[mb]);
            *(__half2*)(sQ + q * A_PAD + d) = h0;
            *(__half2*)(sQ + (q + 8) * A_PAD + d) = h1;
        }
    }
    __syncthreads();

    size_t ob = ((size_t)(bh >> 3) * 512 + (size_t)(bh & 7) * 64) * HW + p0;
    for (int i = tid; i < 4096; i += 128) {
        int d = i >> 6, jj = i & 63;
        __half2 h = __halves2half2(sQ[(jj * 2) * A_PAD + d],
                                   sQ[(jj * 2 + 1) * A_PAD + d]);
        *(__half2*)(g_aoh + ob + (size_t)d * HW + jj * 2) = h;
    }
}

// ---------------- launch ----------------
extern "C" void kernel_launch(void* const* d_in, const int* in_sizes, int n_in,
                              void* d_out, int out_size) {
    (void)in_sizes; (void)n_in; (void)out_size;
    const float* context      = (const float*)d_in[0];
    const float* query_source = (const float*)d_in[1];
    const float* ctx_g = (const float*)d_in[2];
    const float* ctx_b = (const float*)d_in[3];
    const float* qs_g  = (const float*)d_in[4];
    const float* qs_b  = (const float*)d_in[5];
    const float* w_q   = (const float*)d_in[6];
    const float* w_kv  = (const float*)d_in[7];
    const float* w_out = (const float*)d_in[8];
    const float* gamma = (const float*)d_in[9];
    float* out = (float*)d_out;

    static bool inited = false;
    static __half *p_qh, *p_kk, *p_ctxh, *p_qsh, *p_aoh, *p_wq, *p_wkv, *p_wo;
    if (!inited) {
        cudaGetSymbolAddress((void**)&p_qh,   g_qh);
        cudaGetSymbolAddress((void**)&p_kk,   g_kk);
        cudaGetSymbolAddress((void**)&p_ctxh, g_ctxh);
        cudaGetSymbolAddress((void**)&p_qsh,  g_qsh);
        cudaGetSymbolAddress((void**)&p_aoh,  g_aoh);
        cudaGetSymbolAddress((void**)&p_wq,   g_wq);
        cudaGetSymbolAddress((void**)&p_wkv,  g_wkv);
        cudaGetSymbolAddress((void**)&p_wo,   g_wo);
        cudaFuncSetAttribute(proj_gemm_kernel,
                             cudaFuncAttributeMaxDynamicSharedMemorySize, GEMM_SMEM);
        cudaFuncSetAttribute(out_gemm_kernel,
                             cudaFuncAttributeMaxDynamicSharedMemorySize, GEMM_SMEM);
        cudaFuncSetAttribute(vgather_kernel,
                             cudaFuncAttributeMaxDynamicSharedMemorySize, VG_SMEM);
        inited = true;
    }

    // 1) fused channel layernorms + weight conversion
    fused_norm_kernel<<<2048, 256>>>(context, ctx_g, ctx_b, p_ctxh,
                                     query_source, qs_g, qs_b, p_qsh);
    wconv_kernel<<<1024, 256>>>(w_q, w_kv, w_out);

    // 2) merged k + q projections
    proj_gemm_kernel<<<dim3(32, 4, 16), 256, GEMM_SMEM>>>(p_wkv, p_ctxh, p_kk,
                                                          p_wq, p_qsh, p_qh);

    // 3) inverse L2 norms
    inv_norm_kernel<<<2048, 256>>>();

    // 4) pruning statistics + selection
    stats_kernel<<<8192, 256>>>();
    score_topk_kernel<<<64, 64>>>();

    // 5) fused k-gather + v-projection at gathered positions
    vgather_kernel<<<64, 128, VG_SMEM>>>();

    // 6) MMA attention
    attn_kernel<<<dim3(32, 64), 128>>>();

    // 7) out projection + fp16 residual
    out_gemm_kernel<<<dim3(32, 4, 8), 256, GEMM_SMEM>>>(p_wo, p_aoh, out, gamma, p_qsh);
}

// round 13
// speedup vs baseline: 1.0107x; 1.0107x over previous
#include <cuda_runtime.h>
#include <cuda_fp16.h>
#include <math.h>
#include <stdint.h>

#define BATCH 8
#define DIMC  512
#define HW    4096
#define GH    64     // BATCH*HEADS
#define DH    64

// ---------------- scratch (device globals; allocation-free) ----------------
__device__ __align__(128) __half g_qh [BATCH * DIMC * HW];     // q proj fp16 [b][m][p]
__device__ __align__(128) __half g_kk [BATCH * DIMC * HW];     // k proj fp16 [b][m][p]
__device__ __align__(128) __half g_ctxh[BATCH * DIMC * HW];    // normalized ctx fp16
__device__ __align__(128) __half g_qsh [BATCH * DIMC * HW];    // normalized qs fp16 (residual)
__device__ __align__(128) __half g_aoh [BATCH * DIMC * HW];    // attention out fp16
__device__ __align__(128) __half g_wq [512 * 512];
__device__ __align__(128) __half g_wkv[1024 * 512];
__device__ __align__(128) __half g_wo [512 * 512];
__device__ float g_qinv[GH * HW];
__device__ float g_kinv[GH * HW];
__device__ float g_qprobe[GH * DH];
__device__ float g_kh[GH * DH * 64];
__device__ float g_kw[GH * DH * 64];
__device__ int   g_idxh[GH * 8];
__device__ int   g_idxw[GH * 8];
__device__ __half g_kT[GH * 64 * 64];   // [bh][d][j]
__device__ __half g_vf[GH * 64 * 64];   // [bh][j][d]

// ================= warp-MMA helpers =================
__device__ __forceinline__ uint32_t smem_u32(const void* p) {
    uint32_t a;
    asm("{ .reg .u64 t; cvta.to.shared.u64 t, %1; cvt.u32.u64 %0, t; }" : "=r"(a) : "l"(p));
    return a;
}
__device__ __forceinline__ void cp16(uint32_t d, const void* s) {
    asm volatile("cp.async.cg.shared.global [%0], [%1], 16;" :: "r"(d), "l"(s));
}
__device__ __forceinline__ void ldsm4(uint32_t* r, uint32_t a) {
    asm volatile("ldmatrix.sync.aligned.m8n8.x4.shared.b16 {%0,%1,%2,%3}, [%4];"
                 : "=r"(r[0]), "=r"(r[1]), "=r"(r[2]), "=r"(r[3]) : "r"(a));
}
__device__ __forceinline__ void ldsm4t(uint32_t* r, uint32_t a) {
    asm volatile("ldmatrix.sync.aligned.m8n8.x4.trans.shared.b16 {%0,%1,%2,%3}, [%4];"
                 : "=r"(r[0]), "=r"(r[1]), "=r"(r[2]), "=r"(r[3]) : "r"(a));
}
__device__ __forceinline__ void mma16816(float* c, const uint32_t* a, const uint32_t* b) {
    asm volatile(
        "mma.sync.aligned.m16n8k16.row.col.f32.f16.f16.f32 "
        "{%0,%1,%2,%3}, {%4,%5,%6,%7}, {%8,%9}, {%0,%1,%2,%3};"
        : "+f"(c[0]), "+f"(c[1]), "+f"(c[2]), "+f"(c[3])
        : "r"(a[0]), "r"(a[1]), "r"(a[2]), "r"(a[3]), "r"(b[0]), "r"(b[1]));
}

#define A_PAD 72
#define B_PAD 136
#define A_PL  (128 * A_PAD)
#define ST_ELEMS (A_PL + 64 * B_PAD)
#define GEMM_SMEM (3 * ST_ELEMS * 2)

// R11-proven GEMM mainloop (no manual B double-buffer; ptxas schedules it).
#define GEMM_MAINLOOP(copy_chunk)                                                        \
    copy_chunk(0);                                                                       \
    copy_chunk(1);                                                                       \
    for (int c = 0; c < 8; c++) {                                                        \
        if (c < 7) { asm volatile("cp.async.wait_group 1;" ::: "memory"); }              \
        else       { asm volatile("cp.async.wait_group 0;" ::: "memory"); }              \
        __syncthreads();                                                                 \
        if (c < 6) copy_chunk(c + 2);                                                    \
        uint32_t sb = sbase + (uint32_t)(c % 3) * (ST_ELEMS * 2);                        \
        uint32_t a_0 = sb + (uint32_t)((wm + (lane & 15)) * A_PAD + (lane >> 4) * 8) * 2;\
        uint32_t b_0 = sb + (uint32_t)(A_PL + (lane & 15) * B_PAD + wn                   \
                                       + (lane >> 4) * 8) * 2;                           \
        _Pragma("unroll")                                                                \
        for (int kk = 0; kk < 4; kk++) {                                                 \
            uint32_t ah[2][4], bh[4][4];                                                 \
            _Pragma("unroll")                                                            \
            for (int mb = 0; mb < 2; mb++)                                               \
                ldsm4(ah[mb], a_0 + (uint32_t)(mb * 16 * A_PAD + kk * 16) * 2);          \
            _Pragma("unroll")                                                            \
            for (int nt2 = 0; nt2 < 4; nt2++)                                            \
                ldsm4t(bh[nt2], b_0 + (uint32_t)(kk * 16 * B_PAD + nt2 * 16) * 2);       \
            _Pragma("unroll")                                                            \
            for (int mb = 0; mb < 2; mb++)                                               \
                _Pragma("unroll")                                                        \
                for (int nb = 0; nb < 8; nb++)                                           \
                    mma16816(acc[mb][nb], ah[mb], &bh[nb >> 1][(nb & 1) * 2]);           \
        }                                                                                \
    }

// ======== merged q+k projection GEMM: z<8 -> k, z>=8 -> q; fp16 out, M=512 ========
__global__ void __launch_bounds__(256, 2)
proj_gemm_kernel(const __half* __restrict__ Wk, const __half* __restrict__ Xk,
                 __half* __restrict__ Yk,
                 const __half* __restrict__ Wq, const __half* __restrict__ Xq,
                 __half* __restrict__ Yq) {
    extern __shared__ __half sm[];
    uint32_t sbase = smem_u32(sm);
    int tid = threadIdx.x;
    int lane = tid & 31, wid = tid >> 5;
    int z = blockIdx.z;
    const __half *W, *X;
    __half* Yh;
    int b;
    if (z < 8) { W = Wk; X = Xk; Yh = Yk; b = z; }
    else       { W = Wq; X = Xq; Yh = Yq; b = z - 8; }
    int m0 = blockIdx.y * 128, n0 = blockIdx.x * 128;
    const __half* wsrc = W + (size_t)m0 * 512;
    const __half* xsrc = X + (size_t)b * DIMC * HW + n0;

    auto copy_chunk = [&](int c) {
        uint32_t sb = sbase + (uint32_t)(c % 3) * (ST_ELEMS * 2);
#pragma unroll
        for (int i = 0; i < 4; i++) {
            int t = tid + i * 256;
            int m = t >> 3, j = t & 7;
            cp16(sb + (uint32_t)(m * A_PAD + j * 8) * 2,
                 wsrc + (size_t)m * 512 + c * 64 + j * 8);
        }
#pragma unroll
        for (int i = 0; i < 4; i++) {
            int t = tid + i * 256;
            int k = t >> 4, j = t & 15;
            cp16(sb + (uint32_t)(A_PL + k * B_PAD + j * 8) * 2,
                 xsrc + (size_t)(c * 64 + k) * HW + j * 8);
        }
        asm volatile("cp.async.commit_group;" ::: "memory");
    };

    float acc[2][8][4] = {};
    int wm = (wid & 3) * 32;
    int wn = (wid >> 2) * 64;

    GEMM_MAINLOOP(copy_chunk)

    int g = lane >> 2, tig = lane & 3;
#pragma unroll
    for (int mb = 0; mb < 2; mb++) {
#pragma unroll
        for (int nb = 0; nb < 8; nb++) {
            int m = m0 + wm + mb * 16 + g;
            int n = n0 + wn + nb * 8 + tig * 2;
            size_t off0 = ((size_t)b * 512 + m) * HW + n;
            size_t off1 = off0 + (size_t)8 * HW;
            float* p = acc[mb][nb];
            *(__half2*)(Yh + off0) = __floats2half2_rn(p[0], p[1]);
            *(__half2*)(Yh + off1) = __floats2half2_rn(p[2], p[3]);
        }
    }
}

// ======== out-proj GEMM: Y = gamma*(W@X) + addend(fp16), fp32 out, M=512 ========
__global__ void __launch_bounds__(256, 2)
out_gemm_kernel(const __half* __restrict__ W, const __half* __restrict__ X,
                float* __restrict__ Y, const float* __restrict__ gammap,
                const __half* __restrict__ addend) {
    extern __shared__ __half sm[];
    uint32_t sbase = smem_u32(sm);
    int tid = threadIdx.x;
    int lane = tid & 31, wid = tid >> 5;
    int b = blockIdx.z;
    int m0 = blockIdx.y * 128, n0 = blockIdx.x * 128;
    const __half* wsrc = W + (size_t)m0 * 512;
    const __half* xsrc = X + (size_t)b * DIMC * HW + n0;

    auto copy_chunk = [&](int c) {
        uint32_t sb = sbase + (uint32_t)(c % 3) * (ST_ELEMS * 2);
#pragma unroll
        for (int i = 0; i < 4; i++) {
            int t = tid + i * 256;
            int m = t >> 3, j = t & 7;
            cp16(sb + (uint32_t)(m * A_PAD + j * 8) * 2,
                 wsrc + (size_t)m * 512 + c * 64 + j * 8);
        }
#pragma unroll
        for (int i = 0; i < 4; i++) {
            int t = tid + i * 256;
            int k = t >> 4, j = t & 15;
            cp16(sb + (uint32_t)(A_PL + k * B_PAD + j * 8) * 2,
                 xsrc + (size_t)(c * 64 + k) * HW + j * 8);
        }
        asm volatile("cp.async.commit_group;" ::: "memory");
    };

    float acc[2][8][4] = {};
    int wm = (wid & 3) * 32;
    int wn = (wid >> 2) * 64;

    GEMM_MAINLOOP(copy_chunk)

    float ga = gammap[0];
    int g = lane >> 2, tig = lane & 3;
#pragma unroll
    for (int mb = 0; mb < 2; mb++) {
#pragma unroll
        for (int nb = 0; nb < 8; nb++) {
            int m = m0 + wm + mb * 16 + g;
            int n = n0 + wn + nb * 8 + tig * 2;
            size_t off0 = ((size_t)b * 512 + m) * HW + n;
            size_t off1 = off0 + (size_t)8 * HW;
            float* p = acc[mb][nb];
            float2 d0 = __half22float2(*(const __half2*)(addend + off0));
            float2 d1 = __half22float2(*(const __half2*)(addend + off1));
            *(float2*)(Y + off0) = make_float2(ga * p[0] + d0.x, ga * p[1] + d0.y);
            *(float2*)(Y + off1) = make_float2(ga * p[2] + d1.x, ga * p[3] + d1.y);
        }
    }
}

// ======== v-gather GEMM + k-gather: per bh, 256 threads ========
#define VG_APAD 520
#define VG_BOFF (64 * VG_APAD)
#define VG_SMEM ((VG_BOFF + 512 * 72) * 2)
__global__ void __launch_bounds__(256) vgather_kernel() {
    extern __shared__ __half sm[];
    __shared__ int sidx[16];
    uint32_t sbase = smem_u32(sm);
    int tid = threadIdx.x, lane = tid & 31, w = tid >> 5;
    int bh = blockIdx.x;

    if (tid < 8) sidx[tid] = g_idxh[bh * 8 + tid];
    else if (tid < 16) sidx[tid] = g_idxw[bh * 8 + tid - 8];

    // A: wv rows for this head
    const __half* wv = g_wkv + (size_t)(512 + (bh & 7) * 64) * 512;
#pragma unroll
    for (int i = 0; i < 16; i++) {
        int t = tid + i * 256;
        int row = t >> 6, j8 = t & 63;
        cp16(sbase + (uint32_t)(row * VG_APAD + j8 * 8) * 2, wv + row * 512 + j8 * 8);
    }
    asm volatile("cp.async.commit_group;" ::: "memory");
    __syncthreads();                    // sidx visible

    int pj = sidx[(tid & 63) >> 3] * 64 + sidx[8 + (tid & 7)];   // position for j = tid&63

    // kT gather: [d][j]
    {
        const __half* kk = g_kk + (size_t)bh * 64 * HW;
        const float kiv = g_kinv[bh * HW + pj];
#pragma unroll 8
        for (int i = 0; i < 16; i++) {
            int t = tid + i * 256;
            int d = t >> 6, j = t & 63;
            float k = __half2float(kk[(size_t)d * HW + pj]) * kiv;
            g_kT[bh * 4096 + d * 64 + j] = __float2half_rn(k);
        }
    }

    // B: gathered ctx [512 c][64 j]
    const __half* ctx = g_ctxh + (size_t)(bh >> 3) * DIMC * HW;
#pragma unroll 8
    for (int i = 0; i < 128; i++) {
        int t = tid + i * 256;
        int k = t >> 6, j = t & 63;
        sm[VG_BOFF + k * 72 + j] = ctx[(size_t)k * HW + pj];
    }
    asm volatile("cp.async.wait_group 0;" ::: "memory");
    __syncthreads();

    if (w < 4) {
        float acc[8][4] = {};
        uint32_t a_0 = sbase + (uint32_t)((w * 16 + (lane & 15)) * VG_APAD
                                          + (lane >> 4) * 8) * 2;
        uint32_t b_0 = sbase + (uint32_t)(VG_BOFF + (lane & 15) * 72 + (lane >> 4) * 8) * 2;
#pragma unroll 4
        for (int kc = 0; kc < 32; kc++) {
            uint32_t af[4], bf[4][4];
            ldsm4(af, a_0 + (uint32_t)(kc * 16) * 2);
#pragma unroll
            for (int nt2 = 0; nt2 < 4; nt2++)
                ldsm4t(bf[nt2], b_0 + (uint32_t)(kc * 16 * 72 + nt2 * 16) * 2);
#pragma unroll
            for (int nb = 0; nb < 8; nb++)
                mma16816(acc[nb], af, &bf[nb >> 1][(nb & 1) * 2]);
        }

        __half* dst = g_vf + bh * 4096;
        int g = lane >> 2, tig = lane & 3;
        int d0 = w * 16 + g;
#pragma unroll
        for (int nb = 0; nb < 8; nb++) {
            int j0 = nb * 8 + tig * 2;
            float* p = acc[nb];
            dst[j0 * 64 + d0]           = __float2half_rn(p[0]);
            dst[(j0 + 1) * 64 + d0]     = __float2half_rn(p[1]);
            dst[j0 * 64 + d0 + 8]       = __float2half_rn(p[2]);
            dst[(j0 + 1) * 64 + d0 + 8] = __float2half_rn(p[3]);
        }
    }
}

// ---------------- fused channel layernorm (both tensors, one launch) ----------------
__global__ __launch_bounds__(256) void fused_norm_kernel(const float* __restrict__ in0,
                                                         const float* __restrict__ gw0,
                                                         const float* __restrict__ bw0,
                                                         __half* __restrict__ oh0,
                                                         const float* __restrict__ in1,
                                                         const float* __restrict__ gw1,
                                                         const float* __restrict__ bw1,
                                                         __half* __restrict__ oh1) {
    __shared__ float shs[8][32], shq[8][32];
    __shared__ float smean[32], srstd[32];
    int half2nd = blockIdx.x >> 10;
    const float* in = half2nd ? in1 : in0;
    const float* gw = half2nd ? gw1 : gw0;
    const float* bw = half2nd ? bw1 : bw0;
    __half* oh = half2nd ? oh1 : oh0;
    int tid = threadIdx.x;
    int px = tid & 31, cg = tid >> 5;
    int pos = (blockIdx.x & 1023) * 32 + px;
    int b = pos >> 12, sp = pos & 4095;
    size_t base = (size_t)b * DIMC * HW + sp;
    int c0 = cg * 64;
    float v[64];
    float s = 0.f, q = 0.f;
#pragma unroll 8
    for (int c = 0; c < 64; c++) {
        float x = in[base + (size_t)(c0 + c) * HW];
        v[c] = x; s += x; q += x * x;
    }
    shs[cg][px] = s; shq[cg][px] = q;
    __syncthreads();
    if (cg == 0) {
        float ts = 0.f, tq = 0.f;
#pragma unroll
        for (int g = 0; g < 8; g++) { ts += shs[g][px]; tq += shq[g][px]; }
        float mean = ts * (1.0f / 512.0f);
        float var = tq * (1.0f / 512.0f) - mean * mean;
        smean[px] = mean;
        srstd[px] = rsqrtf(var + 1e-5f);
    }
    __syncthreads();
    float m = smean[px], r = srstd[px];
#pragma unroll 8
    for (int c = 0; c < 64; c++) {
        float y = (v[c] - m) * r * gw[c0 + c] + bw[c0 + c];
        oh[base + (size_t)(c0 + c) * HW] = __float2half_rn(y);
    }
}

// ---------------- all weights fp32 -> fp16, one launch ----------------
__global__ __launch_bounds__(256) void wconv_kernel(const float* __restrict__ wq,
                                                    const float* __restrict__ wkv,
                                                    const float* __restrict__ wo) {
    int i4 = (blockIdx.x * 256 + threadIdx.x) * 4;
    const float* src;
    __half* dst;
    int off;
    if (i4 < 262144)       { src = wq;  dst = g_wq;  off = i4; }
    else if (i4 < 786432)  { src = wkv; dst = g_wkv; off = i4 - 262144; }
    else                   { src = wo;  dst = g_wo;  off = i4 - 786432; }
    float4 x = *(const float4*)(src + off);
    *(__half2*)(dst + off)     = __floats2half2_rn(x.x, x.y);
    *(__half2*)(dst + off + 2) = __floats2half2_rn(x.z, x.w);
}

// ---------------- inverse L2 norms for q and k, one launch ----------------
__global__ __launch_bounds__(256) void inv_norm_kernel() {
    int gidx = blockIdx.x * 256 + threadIdx.x;
    int qk = gidx >> 18;
    int idx = gidx & 262143;
    const __half* t = qk ? g_kk : g_qh;
    size_t base = (size_t)(idx >> 12) * (64 * HW) + (idx & 4095);
    float ss = 0.f;
#pragma unroll 8
    for (int d = 0; d < 64; d++) {
        float x = __half2float(t[base + (size_t)d * HW]);
        ss += x * x;
    }
    float r = 1.0f / fmaxf(sqrtf(ss), 1e-12f);
    if (qk == 0) g_qinv[idx] = r; else g_kinv[idx] = r;
}

// ---------------- merged stats: khw (blocks 0..4095) + qprobe (4096..8191) ----------------
__global__ __launch_bounds__(256) void stats_kernel() {
    __shared__ float pl[4096];
    int tid = threadIdx.x;
    if (blockIdx.x < 4096) {
        int bh = blockIdx.x >> 6, c = blockIdx.x & 63;
        size_t base = ((size_t)bh * 64 + c) * HW;
        const float* ki = g_kinv + bh * HW;
        for (int i = tid; i < 2048; i += 256) {
            __half2 h = *(const __half2*)(g_kk + base + 2 * i);
            float2 kv2 = __half22float2(h);
            float2 ki2 = *(const float2*)(ki + 2 * i);
            pl[2 * i]     = fabsf(kv2.x) * ki2.x;
            pl[2 * i + 1] = fabsf(kv2.y) * ki2.y;
        }
        __syncthreads();
        if (tid < 64) {
            int h = tid;
            float s = 0.f;
#pragma unroll 8
            for (int w = 0; w < 64; w++) s += pl[h * 64 + ((w + h) & 63)];
            g_kh[bh * 4096 + c * 64 + h] = s;
        } else if (tid < 128) {
            int w = tid - 64;
            float s = 0.f;
#pragma unroll 8
            for (int h = 0; h < 64; h++) s += pl[h * 64 + w];
            g_kw[bh * 4096 + c * 64 + w] = s;
        }
    } else {
        int bid = blockIdx.x - 4096;
        int g = bid >> 6;
        const __half2* p2 = (const __half2*)(g_qh + (size_t)bid * HW);
        const float2* iv2 = (const float2*)(g_qinv + (size_t)g * HW);
        float s = 0.f;
        for (int i = tid; i < 2048; i += 256) {
            float2 v = __half22float2(p2[i]);
            float2 iv = iv2[i];
            s += fabsf(v.x) * iv.x + fabsf(v.y) * iv.y;
        }
        pl[tid] = s;
        __syncthreads();
        for (int st = 128; st > 0; st >>= 1) {
            if (tid < st) pl[tid] += pl[tid + st];
            __syncthreads();
        }
        if (tid == 0) g_qprobe[bid] = pl[0];
    }
}

// ---------------- scores + top-8 selection ----------------
__global__ __launch_bounds__(64) void score_topk_kernel() {
    int bh = blockIdx.x;
    int h = threadIdx.x;
    __shared__ float sr[64], sc[64];
    float a = 0.f, bb = 0.f;
    for (int c = 0; c < 64; c++) {
        float qp = g_qprobe[bh * 64 + c];
        a  += qp * g_kh[bh * 4096 + c * 64 + h];
        bb += qp * g_kw[bh * 4096 + c * 64 + h];
    }
    sr[h] = a; sc[h] = bb;
    __syncthreads();
    if (h == 0) {
        for (int i = 0; i < 8; i++) {
            float best = -INFINITY; int bi = 0;
            for (int j = 0; j < 64; j++) if (sr[j] > best) { best = sr[j]; bi = j; }
            g_idxh[bh * 8 + i] = bi;
            sr[bi] = -INFINITY;
        }
    } else if (h == 1) {
        for (int i = 0; i < 8; i++) {
            float best = -INFINITY; int bi = 0;
            for (int j = 0; j < 64; j++) if (sc[j] > best) { best = sc[j]; bi = j; }
            g_idxw[bh * 8 + i] = bi;
            sc[bi] = -INFINITY;
        }
    }
}

// ---------------- MMA attention: per (bh, 256-query tile), 256 threads ----------------
#define AT_QOFF 0
#define AT_KOFF (256 * A_PAD)
#define AT_VOFF (AT_KOFF + 64 * A_PAD)
#define AT_SMEM ((AT_VOFF + 64 * A_PAD) * 2)   // ~55 KB
__global__ void __launch_bounds__(256) attn_kernel() {
    extern __shared__ __half sm[];
    __half* sQ = sm + AT_QOFF;
    int tid = threadIdx.x, lane = tid & 31, w = tid >> 5;
    int p0 = blockIdx.x * 256, bh = blockIdx.y;
    uint32_t sQa = smem_u32(sm) + AT_QOFF * 2;
    uint32_t sKa = smem_u32(sm) + AT_KOFF * 2;
    uint32_t sVa = smem_u32(sm) + AT_VOFF * 2;

    const __half* kt = g_kT + bh * 4096;
    const __half* vf = g_vf + bh * 4096;
#pragma unroll
    for (int i = 0; i < 2; i++) {
        int t = tid + i * 256;
        int r = t >> 3, j = t & 7;
        cp16(sKa + (uint32_t)(r * A_PAD + j * 8) * 2, kt + r * 64 + j * 8);
        cp16(sVa + (uint32_t)(r * A_PAD + j * 8) * 2, vf + r * 64 + j * 8);
    }
    asm volatile("cp.async.commit_group;" ::: "memory");

    // Q: fp16 * qinv -> fp16 smem [p][d], 256 positions
    const __half* qp = g_qh + (size_t)bh * 64 * HW + p0;
    const float* qi = g_qinv + bh * HW + p0;
#pragma unroll
    for (int i = 0; i < 32; i++) {
        int t = tid + i * 256;          // 8192 half2 units
        int d2 = t >> 8, p = t & 255;
        float iv = qi[p];
        __half2 h = __floats2half2_rn(__half2float(qp[(size_t)(2 * d2) * HW + p]) * iv,
                                      __half2float(qp[(size_t)(2 * d2 + 1) * HW + p]) * iv);
        *(__half2*)(sQ + p * A_PAD + 2 * d2) = h;
    }
    asm volatile("cp.async.wait_group 0;" ::: "memory");
    __syncthreads();

    // S = Q*K^T : warp w owns query rows w*32..w*32+31
    float sacc[2][8][4] = {};
#pragma unroll
    for (int kk = 0; kk < 4; kk++) {
        uint32_t a[2][4], bk[4][4];
#pragma unroll
        for (int mb = 0; mb < 2; mb++)
            ldsm4(a[mb], sQa + (uint32_t)((w * 32 + mb * 16 + (lane & 15)) * A_PAD
                                          + kk * 16 + (lane >> 4) * 8) * 2);
#pragma unroll
        for (int nt2 = 0; nt2 < 4; nt2++)
            ldsm4t(bk[nt2], sKa + (uint32_t)((kk * 16 + (lane & 15)) * A_PAD
                                             + nt2 * 16 + (lane >> 4) * 8) * 2);
#pragma unroll
        for (int mb = 0; mb < 2; mb++)
#pragma unroll
            for (int nt = 0; nt < 8; nt++)
                mma16816(sacc[mb][nt], a[mb], &bk[nt >> 1][(nt & 1) * 2]);
    }

    // softmax per row
    float is0[2], is1[2];
#pragma unroll
    for (int mb = 0; mb < 2; mb++) {
        float mx0 = -INFINITY, mx1 = -INFINITY;
#pragma unroll
        for (int nt = 0; nt < 8; nt++) {
            mx0 = fmaxf(mx0, fmaxf(sacc[mb][nt][0], sacc[mb][nt][1]));
            mx1 = fmaxf(mx1, fmaxf(sacc[mb][nt][2], sacc[mb][nt][3]));
        }
        mx0 = fmaxf(mx0, __shfl_xor_sync(0xffffffff, mx0, 1));
        mx0 = fmaxf(mx0, __shfl_xor_sync(0xffffffff, mx0, 2));
        mx1 = fmaxf(mx1, __shfl_xor_sync(0xffffffff, mx1, 1));
        mx1 = fmaxf(mx1, __shfl_xor_sync(0xffffffff, mx1, 2));
        float s0 = 0.f, s1 = 0.f;
#pragma unroll
        for (int nt = 0; nt < 8; nt++) {
            sacc[mb][nt][0] = expf(sacc[mb][nt][0] - mx0);
            sacc[mb][nt][1] = expf(sacc[mb][nt][1] - mx0);
            sacc[mb][nt][2] = expf(sacc[mb][nt][2] - mx1);
            sacc[mb][nt][3] = expf(sacc[mb][nt][3] - mx1);
            s0 += sacc[mb][nt][0] + sacc[mb][nt][1];
            s1 += sacc[mb][nt][2] + sacc[mb][nt][3];
        }
        s0 += __shfl_xor_sync(0xffffffff, s0, 1);
        s0 += __shfl_xor_sync(0xffffffff, s0, 2);
        s1 += __shfl_xor_sync(0xffffffff, s1, 1);
        s1 += __shfl_xor_sync(0xffffffff, s1, 2);
        is0[mb] = 1.0f / s0;
        is1[mb] = 1.0f / s1;
    }

    // P a-frags from acc frags
    uint32_t pa[2][4][4];
#pragma unroll
    for (int mb = 0; mb < 2; mb++)
#pragma unroll
        for (int u = 0; u < 4; u++) {
            __half2 h0 = __floats2half2_rn(sacc[mb][2*u][0],   sacc[mb][2*u][1]);
            __half2 h1 = __floats2half2_rn(sacc[mb][2*u][2],   sacc[mb][2*u][3]);
            __half2 h2 = __floats2half2_rn(sacc[mb][2*u+1][0], sacc[mb][2*u+1][1]);
            __half2 h3 = __floats2half2_rn(sacc[mb][2*u+1][2], sacc[mb][2*u+1][3]);
            pa[mb][u][0] = *(uint32_t*)&h0;
            pa[mb][u][1] = *(uint32_t*)&h1;
            pa[mb][u][2] = *(uint32_t*)&h2;
            pa[mb][u][3] = *(uint32_t*)&h3;
        }

    // O = P*V
    float oacc[2][8][4] = {};
#pragma unroll
    for (int u = 0; u < 4; u++) {
        uint32_t bv[4][4];
#pragma unroll
        for (int nt2 = 0; nt2 < 4; nt2++)
            ldsm4t(bv[nt2], sVa + (uint32_t)((u * 16 + (lane & 15)) * A_PAD
                                             + nt2 * 16 + (lane >> 4) * 8) * 2);
#pragma unroll
        for (int mb = 0; mb < 2; mb++)
#pragma unroll
            for (int nt = 0; nt < 8; nt++)
                mma16816(oacc[mb][nt], pa[mb][u], &bv[nt >> 1][(nt & 1) * 2]);
    }

    __syncthreads();   // done reading sQ; reuse as O staging [q][d]
#pragma unroll
    for (int mb = 0; mb < 2; mb++) {
        int q = w * 32 + mb * 16 + (lane >> 2);
#pragma unroll
        for (int nt = 0; nt < 8; nt++) {
            int d = nt * 8 + (lane & 3) * 2;
            __half2 h0 = __floats2half2_rn(oacc[mb][nt][0] * is0[mb],
                                           oacc[mb][nt][1] * is0[mb]);
            __half2 h1 = __floats2half2_rn(oacc[mb][nt][2] * is1[mb],
                                           oacc[mb][nt][3] * is1[mb]);
            *(__half2*)(sQ + q * A_PAD + d) = h0;
            *(__half2*)(sQ + (q + 8) * A_PAD + d) = h1;
        }
    }
    __syncthreads();

    // write O transposed: [d][p], 64 d x 256 p = 8192 half2
    size_t ob = ((size_t)(bh >> 3) * 512 + (size_t)(bh & 7) * 64) * HW + p0;
    for (int i = tid; i < 8192; i += 256) {
        int d = i >> 7, jj = i & 127;
        __half2 h = __halves2half2(sQ[(jj * 2) * A_PAD + d],
                                   sQ[(jj * 2 + 1) * A_PAD + d]);
        *(__half2*)(g_aoh + ob + (size_t)d * HW + jj * 2) = h;
    }
}

// ---------------- launch ----------------
extern "C" void kernel_launch(void* const* d_in, const int* in_sizes, int n_in,
                              void* d_out, int out_size) {
    (void)in_sizes; (void)n_in; (void)out_size;
    const float* context      = (const float*)d_in[0];
    const float* query_source = (const float*)d_in[1];
    const float* ctx_g = (const float*)d_in[2];
    const float* ctx_b = (const float*)d_in[3];
    const float* qs_g  = (const float*)d_in[4];
    const float* qs_b  = (const float*)d_in[5];
    const float* w_q   = (const float*)d_in[6];
    const float* w_kv  = (const float*)d_in[7];
    const float* w_out = (const float*)d_in[8];
    const float* gamma = (const float*)d_in[9];
    float* out = (float*)d_out;

    static bool inited = false;
    static __half *p_qh, *p_kk, *p_ctxh, *p_qsh, *p_aoh, *p_wq, *p_wkv, *p_wo;
    if (!inited) {
        cudaGetSymbolAddress((void**)&p_qh,   g_qh);
        cudaGetSymbolAddress((void**)&p_kk,   g_kk);
        cudaGetSymbolAddress((void**)&p_ctxh, g_ctxh);
        cudaGetSymbolAddress((void**)&p_qsh,  g_qsh);
        cudaGetSymbolAddress((void**)&p_aoh,  g_aoh);
        cudaGetSymbolAddress((void**)&p_wq,   g_wq);
        cudaGetSymbolAddress((void**)&p_wkv,  g_wkv);
        cudaGetSymbolAddress((void**)&p_wo,   g_wo);
        cudaFuncSetAttribute(proj_gemm_kernel,
                             cudaFuncAttributeMaxDynamicSharedMemorySize, GEMM_SMEM);
        cudaFuncSetAttribute(out_gemm_kernel,
                             cudaFuncAttributeMaxDynamicSharedMemorySize, GEMM_SMEM);
        cudaFuncSetAttribute(vgather_kernel,
                             cudaFuncAttributeMaxDynamicSharedMemorySize, VG_SMEM);
        cudaFuncSetAttribute(attn_kernel,
                             cudaFuncAttributeMaxDynamicSharedMemorySize, AT_SMEM);
        inited = true;
    }

    // 1) fused channel layernorms + weight conversion
    fused_norm_kernel<<<2048, 256>>>(context, ctx_g, ctx_b, p_ctxh,
                                     query_source, qs_g, qs_b, p_qsh);
    wconv_kernel<<<1024, 256>>>(w_q, w_kv, w_out);

    // 2) merged k + q projections
    proj_gemm_kernel<<<dim3(32, 4, 16), 256, GEMM_SMEM>>>(p_wkv, p_ctxh, p_kk,
                                                          p_wq, p_qsh, p_qh);

    // 3) inverse L2 norms
    inv_norm_kernel<<<2048, 256>>>();

    // 4) pruning statistics + selection
    stats_kernel<<<8192, 256>>>();
    score_topk_kernel<<<64, 64>>>();

    // 5) fused k-gather + v-projection at gathered positions
    vgather_kernel<<<64, 256, VG_SMEM>>>();

    // 6) MMA attention (256-query tiles)
    attn_kernel<<<dim3(16, 64), 256, AT_SMEM>>>();

    // 7) out projection + fp16 residual
    out_gemm_kernel<<<dim3(32, 4, 8), 256, GEMM_SMEM>>>(p_wo, p_aoh, out, gamma, p_qsh);
}

// round 14
// speedup vs baseline: 1.0417x; 1.0306x over previous
#include <cuda_runtime.h>
#include <cuda_fp16.h>
#include <math.h>
#include <stdint.h>

#define BATCH 8
#define DIMC  512
#define HW    4096
#define GH    64     // BATCH*HEADS
#define DH    64

// ---------------- scratch (device globals; allocation-free) ----------------
__device__ __align__(128) __half g_qh [BATCH * DIMC * HW];     // q proj fp16 [b][m][p]
__device__ __align__(128) __half g_kk [BATCH * DIMC * HW];     // k proj fp16 [b][m][p]
__device__ __align__(128) __half g_ctxh[BATCH * DIMC * HW];    // normalized ctx fp16
__device__ __align__(128) __half g_qsh [BATCH * DIMC * HW];    // normalized qs fp16 (residual)
__device__ __align__(128) __half g_aoh [BATCH * DIMC * HW];    // attention out fp16
__device__ __align__(128) __half g_wq [512 * 512];
__device__ __align__(128) __half g_wkv[1024 * 512];
__device__ __align__(128) __half g_wo [512 * 512];
__device__ float g_qinv[GH * HW];
__device__ float g_kinv[GH * HW];
__device__ float g_qprobe[GH * DH];
__device__ float g_kh[GH * DH * 64];
__device__ float g_kw[GH * DH * 64];
__device__ int   g_idxh[GH * 8];
__device__ int   g_idxw[GH * 8];
__device__ __half g_kT[GH * 64 * 64];   // [bh][d][j]
__device__ __half g_vf[GH * 64 * 64];   // [bh][j][d]

// ================= warp-MMA helpers =================
__device__ __forceinline__ uint32_t smem_u32(const void* p) {
    uint32_t a;
    asm("{ .reg .u64 t; cvta.to.shared.u64 t, %1; cvt.u32.u64 %0, t; }" : "=r"(a) : "l"(p));
    return a;
}
__device__ __forceinline__ void cp16(uint32_t d, const void* s) {
    asm volatile("cp.async.cg.shared.global [%0], [%1], 16;" :: "r"(d), "l"(s));
}
__device__ __forceinline__ void ldsm4(uint32_t* r, uint32_t a) {
    asm volatile("ldmatrix.sync.aligned.m8n8.x4.shared.b16 {%0,%1,%2,%3}, [%4];"
                 : "=r"(r[0]), "=r"(r[1]), "=r"(r[2]), "=r"(r[3]) : "r"(a));
}
__device__ __forceinline__ void ldsm4t(uint32_t* r, uint32_t a) {
    asm volatile("ldmatrix.sync.aligned.m8n8.x4.trans.shared.b16 {%0,%1,%2,%3}, [%4];"
                 : "=r"(r[0]), "=r"(r[1]), "=r"(r[2]), "=r"(r[3]) : "r"(a));
}
__device__ __forceinline__ void mma16816(float* c, const uint32_t* a, const uint32_t* b) {
    asm volatile(
        "mma.sync.aligned.m16n8k16.row.col.f32.f16.f16.f32 "
        "{%0,%1,%2,%3}, {%4,%5,%6,%7}, {%8,%9}, {%0,%1,%2,%3};"
        : "+f"(c[0]), "+f"(c[1]), "+f"(c[2]), "+f"(c[3])
        : "r"(a[0]), "r"(a[1]), "r"(a[2]), "r"(a[3]), "r"(b[0]), "r"(b[1]));
}

#define A_PAD 72
#define B_PAD 136
#define A_PL  (128 * A_PAD)
#define ST_ELEMS (A_PL + 64 * B_PAD)
#define GEMM_SMEM (3 * ST_ELEMS * 2)

// R11-proven GEMM mainloop.
#define GEMM_MAINLOOP(copy_chunk)                                                        \
    copy_chunk(0);                                                                       \
    copy_chunk(1);                                                                       \
    for (int c = 0; c < 8; c++) {                                                        \
        if (c < 7) { asm volatile("cp.async.wait_group 1;" ::: "memory"); }              \
        else       { asm volatile("cp.async.wait_group 0;" ::: "memory"); }              \
        __syncthreads();                                                                 \
        if (c < 6) copy_chunk(c + 2);                                                    \
        uint32_t sb = sbase + (uint32_t)(c % 3) * (ST_ELEMS * 2);                        \
        uint32_t a_0 = sb + (uint32_t)((wm + (lane & 15)) * A_PAD + (lane >> 4) * 8) * 2;\
        uint32_t b_0 = sb + (uint32_t)(A_PL + (lane & 15) * B_PAD + wn                   \
                                       + (lane >> 4) * 8) * 2;                           \
        _Pragma("unroll")                                                                \
        for (int kk = 0; kk < 4; kk++) {                                                 \
            uint32_t ah[2][4], bh[4][4];                                                 \
            _Pragma("unroll")                                                            \
            for (int mb = 0; mb < 2; mb++)                                               \
                ldsm4(ah[mb], a_0 + (uint32_t)(mb * 16 * A_PAD + kk * 16) * 2);          \
            _Pragma("unroll")                                                            \
            for (int nt2 = 0; nt2 < 4; nt2++)                                            \
                ldsm4t(bh[nt2], b_0 + (uint32_t)(kk * 16 * B_PAD + nt2 * 16) * 2);       \
            _Pragma("unroll")                                                            \
            for (int mb = 0; mb < 2; mb++)                                               \
                _Pragma("unroll")                                                        \
                for (int nb = 0; nb < 8; nb++)                                           \
                    mma16816(acc[mb][nb], ah[mb], &bh[nb >> 1][(nb & 1) * 2]);           \
        }                                                                                \
    }

// ======== merged q+k projection GEMM: z<8 -> k, z>=8 -> q; fp16 out, M=512 ========
__global__ void __launch_bounds__(256, 2)
proj_gemm_kernel(const __half* __restrict__ Wk, const __half* __restrict__ Xk,
                 __half* __restrict__ Yk,
                 const __half* __restrict__ Wq, const __half* __restrict__ Xq,
                 __half* __restrict__ Yq) {
    extern __shared__ __half sm[];
    uint32_t sbase = smem_u32(sm);
    int tid = threadIdx.x;
    int lane = tid & 31, wid = tid >> 5;
    int z = blockIdx.z;
    const __half *W, *X;
    __half* Yh;
    int b;
    if (z < 8) { W = Wk; X = Xk; Yh = Yk; b = z; }
    else       { W = Wq; X = Xq; Yh = Yq; b = z - 8; }
    int m0 = blockIdx.y * 128, n0 = blockIdx.x * 128;
    const __half* wsrc = W + (size_t)m0 * 512;
    const __half* xsrc = X + (size_t)b * DIMC * HW + n0;

    auto copy_chunk = [&](int c) {
        uint32_t sb = sbase + (uint32_t)(c % 3) * (ST_ELEMS * 2);
#pragma unroll
        for (int i = 0; i < 4; i++) {
            int t = tid + i * 256;
            int m = t >> 3, j = t & 7;
            cp16(sb + (uint32_t)(m * A_PAD + j * 8) * 2,
                 wsrc + (size_t)m * 512 + c * 64 + j * 8);
        }
#pragma unroll
        for (int i = 0; i < 4; i++) {
            int t = tid + i * 256;
            int k = t >> 4, j = t & 15;
            cp16(sb + (uint32_t)(A_PL + k * B_PAD + j * 8) * 2,
                 xsrc + (size_t)(c * 64 + k) * HW + j * 8);
        }
        asm volatile("cp.async.commit_group;" ::: "memory");
    };

    float acc[2][8][4] = {};
    int wm = (wid & 3) * 32;
    int wn = (wid >> 2) * 64;

    GEMM_MAINLOOP(copy_chunk)

    int g = lane >> 2, tig = lane & 3;
#pragma unroll
    for (int mb = 0; mb < 2; mb++) {
#pragma unroll
        for (int nb = 0; nb < 8; nb++) {
            int m = m0 + wm + mb * 16 + g;
            int n = n0 + wn + nb * 8 + tig * 2;
            size_t off0 = ((size_t)b * 512 + m) * HW + n;
            size_t off1 = off0 + (size_t)8 * HW;
            float* p = acc[mb][nb];
            *(__half2*)(Yh + off0) = __floats2half2_rn(p[0], p[1]);
            *(__half2*)(Yh + off1) = __floats2half2_rn(p[2], p[3]);
        }
    }
}

// ======== out-proj GEMM: Y = gamma*(W@X) + addend(fp16), fp32 out, M=512 ========
__global__ void __launch_bounds__(256, 2)
out_gemm_kernel(const __half* __restrict__ W, const __half* __restrict__ X,
                float* __restrict__ Y, const float* __restrict__ gammap,
                const __half* __restrict__ addend) {
    extern __shared__ __half sm[];
    uint32_t sbase = smem_u32(sm);
    int tid = threadIdx.x;
    int lane = tid & 31, wid = tid >> 5;
    int b = blockIdx.z;
    int m0 = blockIdx.y * 128, n0 = blockIdx.x * 128;
    const __half* wsrc = W + (size_t)m0 * 512;
    const __half* xsrc = X + (size_t)b * DIMC * HW + n0;

    auto copy_chunk = [&](int c) {
        uint32_t sb = sbase + (uint32_t)(c % 3) * (ST_ELEMS * 2);
#pragma unroll
        for (int i = 0; i < 4; i++) {
            int t = tid + i * 256;
            int m = t >> 3, j = t & 7;
            cp16(sb + (uint32_t)(m * A_PAD + j * 8) * 2,
                 wsrc + (size_t)m * 512 + c * 64 + j * 8);
        }
#pragma unroll
        for (int i = 0; i < 4; i++) {
            int t = tid + i * 256;
            int k = t >> 4, j = t & 15;
            cp16(sb + (uint32_t)(A_PL + k * B_PAD + j * 8) * 2,
                 xsrc + (size_t)(c * 64 + k) * HW + j * 8);
        }
        asm volatile("cp.async.commit_group;" ::: "memory");
    };

    float acc[2][8][4] = {};
    int wm = (wid & 3) * 32;
    int wn = (wid >> 2) * 64;

    GEMM_MAINLOOP(copy_chunk)

    float ga = gammap[0];
    int g = lane >> 2, tig = lane & 3;
#pragma unroll
    for (int mb = 0; mb < 2; mb++) {
#pragma unroll
        for (int nb = 0; nb < 8; nb++) {
            int m = m0 + wm + mb * 16 + g;
            int n = n0 + wn + nb * 8 + tig * 2;
            size_t off0 = ((size_t)b * 512 + m) * HW + n;
            size_t off1 = off0 + (size_t)8 * HW;
            float* p = acc[mb][nb];
            float2 d0 = __half22float2(*(const __half2*)(addend + off0));
            float2 d1 = __half22float2(*(const __half2*)(addend + off1));
            *(float2*)(Y + off0) = make_float2(ga * p[0] + d0.x, ga * p[1] + d0.y);
            *(float2*)(Y + off1) = make_float2(ga * p[2] + d1.x, ga * p[3] + d1.y);
        }
    }
}

// ======== v-gather GEMM: per bh, V[j][d] = sum_c wv[d,c]*ctx[c,p_j] (R11 form) ========
#define VG_APAD 520
#define VG_BOFF (64 * VG_APAD)
#define VG_SMEM ((VG_BOFF + 512 * 72) * 2)
__global__ void __launch_bounds__(128) vgather_kernel() {
    extern __shared__ __half sm[];
    __shared__ int sidx[16];
    uint32_t sbase = smem_u32(sm);
    int tid = threadIdx.x, lane = tid & 31, w = tid >> 5;
    int bh = blockIdx.x;

    if (tid < 8) sidx[tid] = g_idxh[bh * 8 + tid];
    else if (tid < 16) sidx[tid] = g_idxw[bh * 8 + tid - 8];

    const __half* wv = g_wkv + (size_t)(512 + (bh & 7) * 64) * 512;
#pragma unroll
    for (int i = 0; i < 32; i++) {
        int t = tid + i * 128;
        int row = t >> 6, j8 = t & 63;
        cp16(sbase + (uint32_t)(row * VG_APAD + j8 * 8) * 2, wv + row * 512 + j8 * 8);
    }
    asm volatile("cp.async.commit_group;" ::: "memory");
    __syncthreads();

    const __half* ctx = g_ctxh + (size_t)(bh >> 3) * DIMC * HW;
    int pj = sidx[(tid & 63) >> 3] * 64 + sidx[8 + (tid & 7)];
#pragma unroll 8
    for (int i = 0; i < 256; i++) {
        int t = tid + i * 128;
        int k = t >> 6, j = t & 63;
        sm[VG_BOFF + k * 72 + j] = ctx[(size_t)k * HW + pj];
    }
    asm volatile("cp.async.wait_group 0;" ::: "memory");
    __syncthreads();

    float acc[8][4] = {};
    uint32_t a_0 = sbase + (uint32_t)((w * 16 + (lane & 15)) * VG_APAD + (lane >> 4) * 8) * 2;
    uint32_t b_0 = sbase + (uint32_t)(VG_BOFF + (lane & 15) * 72 + (lane >> 4) * 8) * 2;
#pragma unroll 4
    for (int kc = 0; kc < 32; kc++) {
        uint32_t af[4], bf[4][4];
        ldsm4(af, a_0 + (uint32_t)(kc * 16) * 2);
#pragma unroll
        for (int nt2 = 0; nt2 < 4; nt2++)
            ldsm4t(bf[nt2], b_0 + (uint32_t)(kc * 16 * 72 + nt2 * 16) * 2);
#pragma unroll
        for (int nb = 0; nb < 8; nb++)
            mma16816(acc[nb], af, &bf[nb >> 1][(nb & 1) * 2]);
    }

    __half* dst = g_vf + bh * 4096;
    int g = lane >> 2, tig = lane & 3;
    int d0 = w * 16 + g;
#pragma unroll
    for (int nb = 0; nb < 8; nb++) {
        int j0 = nb * 8 + tig * 2;
        float* p = acc[nb];
        dst[j0 * 64 + d0]           = __float2half_rn(p[0]);
        dst[(j0 + 1) * 64 + d0]     = __float2half_rn(p[1]);
        dst[j0 * 64 + d0 + 8]       = __float2half_rn(p[2]);
        dst[(j0 + 1) * 64 + d0 + 8] = __float2half_rn(p[3]);
    }
}

// ---------------- fused channel layernorm (both tensors) + weight conversion ----------------
__global__ __launch_bounds__(256) void fused_norm_kernel(const float* __restrict__ in0,
                                                         const float* __restrict__ gw0,
                                                         const float* __restrict__ bw0,
                                                         __half* __restrict__ oh0,
                                                         const float* __restrict__ in1,
                                                         const float* __restrict__ gw1,
                                                         const float* __restrict__ bw1,
                                                         __half* __restrict__ oh1,
                                                         const float* __restrict__ wq,
                                                         const float* __restrict__ wkv,
                                                         const float* __restrict__ wo) {
    if (blockIdx.x >= 2048) {
        // weight fp32 -> fp16 (1024 blocks x 256 threads x 4 elems = 1,048,576)
        int i4 = ((blockIdx.x - 2048) * 256 + threadIdx.x) * 4;
        const float* src;
        __half* dst;
        int off;
        if (i4 < 262144)       { src = wq;  dst = g_wq;  off = i4; }
        else if (i4 < 786432)  { src = wkv; dst = g_wkv; off = i4 - 262144; }
        else                   { src = wo;  dst = g_wo;  off = i4 - 786432; }
        float4 x = *(const float4*)(src + off);
        *(__half2*)(dst + off)     = __floats2half2_rn(x.x, x.y);
        *(__half2*)(dst + off + 2) = __floats2half2_rn(x.z, x.w);
        return;
    }
    __shared__ float shs[8][32], shq[8][32];
    __shared__ float smean[32], srstd[32];
    int half2nd = blockIdx.x >> 10;
    const float* in = half2nd ? in1 : in0;
    const float* gw = half2nd ? gw1 : gw0;
    const float* bw = half2nd ? bw1 : bw0;
    __half* oh = half2nd ? oh1 : oh0;
    int tid = threadIdx.x;
    int px = tid & 31, cg = tid >> 5;
    int pos = (blockIdx.x & 1023) * 32 + px;
    int b = pos >> 12, sp = pos & 4095;
    size_t base = (size_t)b * DIMC * HW + sp;
    int c0 = cg * 64;
    float v[64];
    float s = 0.f, q = 0.f;
#pragma unroll 8
    for (int c = 0; c < 64; c++) {
        float x = in[base + (size_t)(c0 + c) * HW];
        v[c] = x; s += x; q += x * x;
    }
    shs[cg][px] = s; shq[cg][px] = q;
    __syncthreads();
    if (cg == 0) {
        float ts = 0.f, tq = 0.f;
#pragma unroll
        for (int g = 0; g < 8; g++) { ts += shs[g][px]; tq += shq[g][px]; }
        float mean = ts * (1.0f / 512.0f);
        float var = tq * (1.0f / 512.0f) - mean * mean;
        smean[px] = mean;
        srstd[px] = rsqrtf(var + 1e-5f);
    }
    __syncthreads();
    float m = smean[px], r = srstd[px];
#pragma unroll 8
    for (int c = 0; c < 64; c++) {
        float y = (v[c] - m) * r * gw[c0 + c] + bw[c0 + c];
        oh[base + (size_t)(c0 + c) * HW] = __float2half_rn(y);
    }
}

// ---------------- inverse L2 norms for q and k (half2, 2 positions/thread) ----------------
__global__ __launch_bounds__(256) void inv_norm_kernel() {
    int gidx = blockIdx.x * 256 + threadIdx.x;    // 262144 = 2 tensors * 131072 pos-pairs
    int qk = gidx >> 17;                          // 0: q, 1: k
    int id2 = gidx & 131071;
    int g = id2 >> 11, p2 = id2 & 2047;
    const __half* t = qk ? g_kk : g_qh;
    size_t base = (size_t)g * (64 * HW) + 2 * p2;
    float sx = 0.f, sy = 0.f;
#pragma unroll 8
    for (int d = 0; d < 64; d++) {
        float2 x = __half22float2(*(const __half2*)(t + base + (size_t)d * HW));
        sx += x.x * x.x;
        sy += x.y * x.y;
    }
    float2 r = make_float2(1.0f / fmaxf(sqrtf(sx), 1e-12f),
                           1.0f / fmaxf(sqrtf(sy), 1e-12f));
    float* dst = qk ? g_kinv : g_qinv;
    *(float2*)(dst + g * HW + 2 * p2) = r;
}

// ---------------- merged stats: khw (blocks 0..4095) + qprobe (4096..8191) ----------------
__global__ __launch_bounds__(256) void stats_kernel() {
    __shared__ float pl[4096];
    int tid = threadIdx.x;
    if (blockIdx.x < 4096) {
        int bh = blockIdx.x >> 6, c = blockIdx.x & 63;
        size_t base = ((size_t)bh * 64 + c) * HW;
        const float* ki = g_kinv + bh * HW;
        for (int i = tid; i < 2048; i += 256) {
            __half2 h = *(const __half2*)(g_kk + base + 2 * i);
            float2 kv2 = __half22float2(h);
            float2 ki2 = *(const float2*)(ki + 2 * i);
            pl[2 * i]     = fabsf(kv2.x) * ki2.x;
            pl[2 * i + 1] = fabsf(kv2.y) * ki2.y;
        }
        __syncthreads();
        if (tid < 64) {
            int h = tid;
            float s = 0.f;
#pragma unroll 8
            for (int w = 0; w < 64; w++) s += pl[h * 64 + ((w + h) & 63)];
            g_kh[bh * 4096 + c * 64 + h] = s;
        } else if (tid < 128) {
            int w = tid - 64;
            float s = 0.f;
#pragma unroll 8
            for (int h = 0; h < 64; h++) s += pl[h * 64 + w];
            g_kw[bh * 4096 + c * 64 + w] = s;
        }
    } else {
        int bid = blockIdx.x - 4096;
        int g = bid >> 6;
        const __half2* p2 = (const __half2*)(g_qh + (size_t)bid * HW);
        const float2* iv2 = (const float2*)(g_qinv + (size_t)g * HW);
        float s = 0.f;
        for (int i = tid; i < 2048; i += 256) {
            float2 v = __half22float2(p2[i]);
            float2 iv = iv2[i];
            s += fabsf(v.x) * iv.x + fabsf(v.y) * iv.y;
        }
        pl[tid] = s;
        __syncthreads();
        for (int st = 128; st > 0; st >>= 1) {
            if (tid < st) pl[tid] += pl[tid + st];
            __syncthreads();
        }
        if (tid == 0) g_qprobe[bid] = pl[0];
    }
}

// ---------------- scores + top-8 selection ----------------
__global__ __launch_bounds__(64) void score_topk_kernel() {
    int bh = blockIdx.x;
    int h = threadIdx.x;
    __shared__ float sr[64], sc[64];
    float a = 0.f, bb = 0.f;
    for (int c = 0; c < 64; c++) {
        float qp = g_qprobe[bh * 64 + c];
        a  += qp * g_kh[bh * 4096 + c * 64 + h];
        bb += qp * g_kw[bh * 4096 + c * 64 + h];
    }
    sr[h] = a; sc[h] = bb;
    __syncthreads();
    if (h == 0) {
        for (int i = 0; i < 8; i++) {
            float best = -INFINITY; int bi = 0;
            for (int j = 0; j < 64; j++) if (sr[j] > best) { best = sr[j]; bi = j; }
            g_idxh[bh * 8 + i] = bi;
            sr[bi] = -INFINITY;
        }
    } else if (h == 1) {
        for (int i = 0; i < 8; i++) {
            float best = -INFINITY; int bi = 0;
            for (int j = 0; j < 64; j++) if (sc[j] > best) { best = sc[j]; bi = j; }
            g_idxw[bh * 8 + i] = bi;
            sc[bi] = -INFINITY;
        }
    }
}

// ---------------- gather pruned k -> kT fp16 tile (R11 form) ----------------
__global__ __launch_bounds__(256) void gather_kernel() {
    int idx = blockIdx.x * 256 + threadIdx.x;   // 262144
    int bh = idx >> 12, r = (idx >> 6) & 63, cc = idx & 63;
    int hh = g_idxh[bh * 8 + (cc >> 3)];
    int ww = g_idxw[bh * 8 + (cc & 7)];
    int p = hh * 64 + ww;
    float k = __half2float(g_kk[((size_t)bh * 64 + r) * HW + p]) * g_kinv[bh * HW + p];
    g_kT[idx] = __float2half_rn(k);
}

// ---------------- MMA attention: per (bh, 128-query tile) (R11 form) ----------------
__global__ __launch_bounds__(128) void attn_kernel() {
    __shared__ __half sQ[128 * A_PAD];
    __shared__ __half sK[64 * A_PAD];
    __shared__ __half sV[64 * A_PAD];
    int tid = threadIdx.x, lane = tid & 31, w = tid >> 5;
    int p0 = blockIdx.x * 128, bh = blockIdx.y;
    uint32_t sQa = smem_u32(sQ), sKa = smem_u32(sK), sVa = smem_u32(sV);

    const __half* kt = g_kT + bh * 4096;
    const __half* vf = g_vf + bh * 4096;
#pragma unroll
    for (int i = 0; i < 4; i++) {
        int t = tid + i * 128;
        int r = t >> 3, j = t & 7;
        cp16(sKa + (uint32_t)(r * A_PAD + j * 8) * 2, kt + r * 64 + j * 8);
        cp16(sVa + (uint32_t)(r * A_PAD + j * 8) * 2, vf + r * 64 + j * 8);
    }
    asm volatile("cp.async.commit_group;" ::: "memory");

    const __half* qp = g_qh + (size_t)bh * 64 * HW + p0;
    const float* qi = g_qinv + bh * HW + p0;
#pragma unroll
    for (int i = 0; i < 32; i++) {
        int t = tid + i * 128;
        int d2 = t >> 7, p = t & 127;
        float iv = qi[p];
        __half2 h = __floats2half2_rn(__half2float(qp[(size_t)(2 * d2) * HW + p]) * iv,
                                      __half2float(qp[(size_t)(2 * d2 + 1) * HW + p]) * iv);
        *(__half2*)(sQ + p * A_PAD + 2 * d2) = h;
    }
    asm volatile("cp.async.wait_group 0;" ::: "memory");
    __syncthreads();

    float sacc[2][8][4] = {};
#pragma unroll
    for (int kk = 0; kk < 4; kk++) {
        uint32_t a[2][4], bk[4][4];
#pragma unroll
        for (int mb = 0; mb < 2; mb++)
            ldsm4(a[mb], sQa + (uint32_t)((w * 32 + mb * 16 + (lane & 15)) * A_PAD
                                          + kk * 16 + (lane >> 4) * 8) * 2);
#pragma unroll
        for (int nt2 = 0; nt2 < 4; nt2++)
            ldsm4t(bk[nt2], sKa + (uint32_t)((kk * 16 + (lane & 15)) * A_PAD
                                             + nt2 * 16 + (lane >> 4) * 8) * 2);
#pragma unroll
        for (int mb = 0; mb < 2; mb++)
#pragma unroll
            for (int nt = 0; nt < 8; nt++)
                mma16816(sacc[mb][nt], a[mb], &bk[nt >> 1][(nt & 1) * 2]);
    }

    float is0[2], is1[2];
#pragma unroll
    for (int mb = 0; mb < 2; mb++) {
        float mx0 = -INFINITY, mx1 = -INFINITY;
#pragma unroll
        for (int nt = 0; nt < 8; nt++) {
            mx0 = fmaxf(mx0, fmaxf(sacc[mb][nt][0], sacc[mb][nt][1]));
            mx1 = fmaxf(mx1, fmaxf(sacc[mb][nt][2], sacc[mb][nt][3]));
        }
        mx0 = fmaxf(mx0, __shfl_xor_sync(0xffffffff, mx0, 1));
        mx0 = fmaxf(mx0, __shfl_xor_sync(0xffffffff, mx0, 2));
        mx1 = fmaxf(mx1, __shfl_xor_sync(0xffffffff, mx1, 1));
        mx1 = fmaxf(mx1, __shfl_xor_sync(0xffffffff, mx1, 2));
        float s0 = 0.f, s1 = 0.f;
#pragma unroll
        for (int nt = 0; nt < 8; nt++) {
            sacc[mb][nt][0] = expf(sacc[mb][nt][0] - mx0);
            sacc[mb][nt][1] = expf(sacc[mb][nt][1] - mx0);
            sacc[mb][nt][2] = expf(sacc[mb][nt][2] - mx1);
            sacc[mb][nt][3] = expf(sacc[mb][nt][3] - mx1);
            s0 += sacc[mb][nt][0] + sacc[mb][nt][1];
            s1 += sacc[mb][nt][2] + sacc[mb][nt][3];
        }
        s0 += __shfl_xor_sync(0xffffffff, s0, 1);
        s0 += __shfl_xor_sync(0xffffffff, s0, 2);
        s1 += __shfl_xor_sync(0xffffffff, s1, 1);
        s1 += __shfl_xor_sync(0xffffffff, s1, 2);
        is0[mb] = 1.0f / s0;
        is1[mb] = 1.0f / s1;
    }

    uint32_t pa[2][4][4];
#pragma unroll
    for (int mb = 0; mb < 2; mb++)
#pragma unroll
        for (int u = 0; u < 4; u++) {
            __half2 h0 = __floats2half2_rn(sacc[mb][2*u][0],   sacc[mb][2*u][1]);
            __half2 h1 = __floats2half2_rn(sacc[mb][2*u][2],   sacc[mb][2*u][3]);
            __half2 h2 = __floats2half2_rn(sacc[mb][2*u+1][0], sacc[mb][2*u+1][1]);
            __half2 h3 = __floats2half2_rn(sacc[mb][2*u+1][2], sacc[mb][2*u+1][3]);
            pa[mb][u][0] = *(uint32_t*)&h0;
            pa[mb][u][1] = *(uint32_t*)&h1;
            pa[mb][u][2] = *(uint32_t*)&h2;
            pa[mb][u][3] = *(uint32_t*)&h3;
        }

    float oacc[2][8][4] = {};
#pragma unroll
    for (int u = 0; u < 4; u++) {
        uint32_t bv[4][4];
#pragma unroll
        for (int nt2 = 0; nt2 < 4; nt2++)
            ldsm4t(bv[nt2], sVa + (uint32_t)((u * 16 + (lane & 15)) * A_PAD
                                             + nt2 * 16 + (lane >> 4) * 8) * 2);
#pragma unroll
        for (int mb = 0; mb < 2; mb++)
#pragma unroll
            for (int nt = 0; nt < 8; nt++)
                mma16816(oacc[mb][nt], pa[mb][u], &bv[nt >> 1][(nt & 1) * 2]);
    }

    __syncthreads();
#pragma unroll
    for (int mb = 0; mb < 2; mb++) {
        int q = w * 32 + mb * 16 + (lane >> 2);
#pragma unroll
        for (int nt = 0; nt < 8; nt++) {
            int d = nt * 8 + (lane & 3) * 2;
            __half2 h0 = __floats2half2_rn(oacc[mb][nt][0] * is0[mb],
                                           oacc[mb][nt][1] * is0[mb]);
            __half2 h1 = __floats2half2_rn(oacc[mb][nt][2] * is1[mb],
                                           oacc[mb][nt][3] * is1[mb]);
            *(__half2*)(sQ + q * A_PAD + d) = h0;
            *(__half2*)(sQ + (q + 8) * A_PAD + d) = h1;
        }
    }
    __syncthreads();

    size_t ob = ((size_t)(bh >> 3) * 512 + (size_t)(bh & 7) * 64) * HW + p0;
    for (int i = tid; i < 4096; i += 128) {
        int d = i >> 6, jj = i & 63;
        __half2 h = __halves2half2(sQ[(jj * 2) * A_PAD + d],
                                   sQ[(jj * 2 + 1) * A_PAD + d]);
        *(__half2*)(g_aoh + ob + (size_t)d * HW + jj * 2) = h;
    }
}

// ---------------- launch ----------------
extern "C" void kernel_launch(void* const* d_in, const int* in_sizes, int n_in,
                              void* d_out, int out_size) {
    (void)in_sizes; (void)n_in; (void)out_size;
    const float* context      = (const float*)d_in[0];
    const float* query_source = (const float*)d_in[1];
    const float* ctx_g = (const float*)d_in[2];
    const float* ctx_b = (const float*)d_in[3];
    const float* qs_g  = (const float*)d_in[4];
    const float* qs_b  = (const float*)d_in[5];
    const float* w_q   = (const float*)d_in[6];
    const float* w_kv  = (const float*)d_in[7];
    const float* w_out = (const float*)d_in[8];
    const float* gamma = (const float*)d_in[9];
    float* out = (float*)d_out;

    static bool inited = false;
    static __half *p_qh, *p_kk, *p_ctxh, *p_qsh, *p_aoh, *p_wq, *p_wkv, *p_wo;
    if (!inited) {
        cudaGetSymbolAddress((void**)&p_qh,   g_qh);
        cudaGetSymbolAddress((void**)&p_kk,   g_kk);
        cudaGetSymbolAddress((void**)&p_ctxh, g_ctxh);
        cudaGetSymbolAddress((void**)&p_qsh,  g_qsh);
        cudaGetSymbolAddress((void**)&p_aoh,  g_aoh);
        cudaGetSymbolAddress((void**)&p_wq,   g_wq);
        cudaGetSymbolAddress((void**)&p_wkv,  g_wkv);
        cudaGetSymbolAddress((void**)&p_wo,   g_wo);
        cudaFuncSetAttribute(proj_gemm_kernel,
                             cudaFuncAttributeMaxDynamicSharedMemorySize, GEMM_SMEM);
        cudaFuncSetAttribute(out_gemm_kernel,
                             cudaFuncAttributeMaxDynamicSharedMemorySize, GEMM_SMEM);
        cudaFuncSetAttribute(vgather_kernel,
                             cudaFuncAttributeMaxDynamicSharedMemorySize, VG_SMEM);
        inited = true;
    }

    // 1) fused channel layernorms + weight conversion (one launch)
    fused_norm_kernel<<<3072, 256>>>(context, ctx_g, ctx_b, p_ctxh,
                                     query_source, qs_g, qs_b, p_qsh,
                                     w_q, w_kv, w_out);

    // 2) merged k + q projections
    proj_gemm_kernel<<<dim3(32, 4, 16), 256, GEMM_SMEM>>>(p_wkv, p_ctxh, p_kk,
                                                          p_wq, p_qsh, p_qh);

    // 3) inverse L2 norms (half2)
    inv_norm_kernel<<<1024, 256>>>();

    // 4) pruning statistics + selection
    stats_kernel<<<8192, 256>>>();
    score_topk_kernel<<<64, 64>>>();

    // 5) gather k^T; compute V only at gathered positions
    gather_kernel<<<1024, 256>>>();
    vgather_kernel<<<64, 128, VG_SMEM>>>();

    // 6) MMA attention
    attn_kernel<<<dim3(32, 64), 128>>>();

    // 7) out projection + fp16 residual
    out_gemm_kernel<<<dim3(32, 4, 8), 256, GEMM_SMEM>>>(p_wo, p_aoh, out, gamma, p_qsh);
}

// round 15
// speedup vs baseline: 1.0701x; 1.0273x over previous
#include <cuda_runtime.h>
#include <cuda_fp16.h>
#include <math.h>
#include <stdint.h>

#define BATCH 8
#define DIMC  512
#define HW    4096
#define GH    64     // BATCH*HEADS
#define DH    64

// ---------------- scratch (device globals; allocation-free) ----------------
__device__ __align__(128) __half g_qh [BATCH * DIMC * HW];     // q proj fp16 [b][m][p]
__device__ __align__(128) __half g_kk [BATCH * DIMC * HW];     // k proj fp16 [b][m][p]
__device__ __align__(128) __half g_ctxh[BATCH * DIMC * HW];    // normalized ctx fp16
__device__ __align__(128) __half g_qsh [BATCH * DIMC * HW];    // normalized qs fp16 (residual)
__device__ __align__(128) __half g_aoh [BATCH * DIMC * HW];    // attention out fp16
__device__ __align__(128) __half g_wq [512 * 512];
__device__ __align__(128) __half g_wkv[1024 * 512];
__device__ __align__(128) __half g_wo [512 * 512];
__device__ float g_qinv[GH * HW];
__device__ float g_kinv[GH * HW];
__device__ float g_qprobe[GH * DH];
__device__ float g_kh[GH * DH * 64];
__device__ float g_kw[GH * DH * 64];
__device__ int   g_idxh[GH * 8];
__device__ int   g_idxw[GH * 8];
__device__ __half g_kT[GH * 64 * 64];   // [bh][d][j]
__device__ __half g_vf[GH * 64 * 64];   // [bh][j][d]

// ================= warp-MMA helpers =================
__device__ __forceinline__ uint32_t smem_u32(const void* p) {
    uint32_t a;
    asm("{ .reg .u64 t; cvta.to.shared.u64 t, %1; cvt.u32.u64 %0, t; }" : "=r"(a) : "l"(p));
    return a;
}
__device__ __forceinline__ void cp16(uint32_t d, const void* s) {
    asm volatile("cp.async.cg.shared.global [%0], [%1], 16;" :: "r"(d), "l"(s));
}
__device__ __forceinline__ void ldsm4(uint32_t* r, uint32_t a) {
    asm volatile("ldmatrix.sync.aligned.m8n8.x4.shared.b16 {%0,%1,%2,%3}, [%4];"
                 : "=r"(r[0]), "=r"(r[1]), "=r"(r[2]), "=r"(r[3]) : "r"(a));
}
__device__ __forceinline__ void ldsm4t(uint32_t* r, uint32_t a) {
    asm volatile("ldmatrix.sync.aligned.m8n8.x4.trans.shared.b16 {%0,%1,%2,%3}, [%4];"
                 : "=r"(r[0]), "=r"(r[1]), "=r"(r[2]), "=r"(r[3]) : "r"(a));
}
__device__ __forceinline__ void mma16816(float* c, const uint32_t* a, const uint32_t* b) {
    asm volatile(
        "mma.sync.aligned.m16n8k16.row.col.f32.f16.f16.f32 "
        "{%0,%1,%2,%3}, {%4,%5,%6,%7}, {%8,%9}, {%0,%1,%2,%3};"
        : "+f"(c[0]), "+f"(c[1]), "+f"(c[2]), "+f"(c[3])
        : "r"(a[0]), "r"(a[1]), "r"(a[2]), "r"(a[3]), "r"(b[0]), "r"(b[1]));
}

#define A_PAD 72
#define B_PAD 136
#define A_PL  (128 * A_PAD)
#define ST_ELEMS (A_PL + 64 * B_PAD)
#define GEMM_SMEM (3 * ST_ELEMS * 2)

// R11-proven GEMM mainloop.
#define GEMM_MAINLOOP(copy_chunk)                                                        \
    copy_chunk(0);                                                                       \
    copy_chunk(1);                                                                       \
    for (int c = 0; c < 8; c++) {                                                        \
        if (c < 7) { asm volatile("cp.async.wait_group 1;" ::: "memory"); }              \
        else       { asm volatile("cp.async.wait_group 0;" ::: "memory"); }              \
        __syncthreads();                                                                 \
        if (c < 6) copy_chunk(c + 2);                                                    \
        uint32_t sb = sbase + (uint32_t)(c % 3) * (ST_ELEMS * 2);                        \
        uint32_t a_0 = sb + (uint32_t)((wm + (lane & 15)) * A_PAD + (lane >> 4) * 8) * 2;\
        uint32_t b_0 = sb + (uint32_t)(A_PL + (lane & 15) * B_PAD + wn                   \
                                       + (lane >> 4) * 8) * 2;                           \
        _Pragma("unroll")                                                                \
        for (int kk = 0; kk < 4; kk++) {                                                 \
            uint32_t ah[2][4], bh[4][4];                                                 \
            _Pragma("unroll")                                                            \
            for (int mb = 0; mb < 2; mb++)                                               \
                ldsm4(ah[mb], a_0 + (uint32_t)(mb * 16 * A_PAD + kk * 16) * 2);          \
            _Pragma("unroll")                                                            \
            for (int nt2 = 0; nt2 < 4; nt2++)                                            \
                ldsm4t(bh[nt2], b_0 + (uint32_t)(kk * 16 * B_PAD + nt2 * 16) * 2);       \
            _Pragma("unroll")                                                            \
            for (int mb = 0; mb < 2; mb++)                                               \
                _Pragma("unroll")                                                        \
                for (int nb = 0; nb < 8; nb++)                                           \
                    mma16816(acc[mb][nb], ah[mb], &bh[nb >> 1][(nb & 1) * 2]);           \
        }                                                                                \
    }

// ======== merged q+k projection GEMM: z<8 -> k, z>=8 -> q; fp16 out, M=512 ========
__global__ void __launch_bounds__(256, 2)
proj_gemm_kernel(const __half* __restrict__ Wk, const __half* __restrict__ Xk,
                 __half* __restrict__ Yk,
                 const __half* __restrict__ Wq, const __half* __restrict__ Xq,
                 __half* __restrict__ Yq) {
    extern __shared__ __half sm[];
    uint32_t sbase = smem_u32(sm);
    int tid = threadIdx.x;
    int lane = tid & 31, wid = tid >> 5;
    int z = blockIdx.z;
    const __half *W, *X;
    __half* Yh;
    int b;
    if (z < 8) { W = Wk; X = Xk; Yh = Yk; b = z; }
    else       { W = Wq; X = Xq; Yh = Yq; b = z - 8; }
    int m0 = blockIdx.y * 128, n0 = blockIdx.x * 128;
    const __half* wsrc = W + (size_t)m0 * 512;
    const __half* xsrc = X + (size_t)b * DIMC * HW + n0;

    auto copy_chunk = [&](int c) {
        uint32_t sb = sbase + (uint32_t)(c % 3) * (ST_ELEMS * 2);
#pragma unroll
        for (int i = 0; i < 4; i++) {
            int t = tid + i * 256;
            int m = t >> 3, j = t & 7;
            cp16(sb + (uint32_t)(m * A_PAD + j * 8) * 2,
                 wsrc + (size_t)m * 512 + c * 64 + j * 8);
        }
#pragma unroll
        for (int i = 0; i < 4; i++) {
            int t = tid + i * 256;
            int k = t >> 4, j = t & 15;
            cp16(sb + (uint32_t)(A_PL + k * B_PAD + j * 8) * 2,
                 xsrc + (size_t)(c * 64 + k) * HW + j * 8);
        }
        asm volatile("cp.async.commit_group;" ::: "memory");
    };

    float acc[2][8][4] = {};
    int wm = (wid & 3) * 32;
    int wn = (wid >> 2) * 64;

    GEMM_MAINLOOP(copy_chunk)

    int g = lane >> 2, tig = lane & 3;
#pragma unroll
    for (int mb = 0; mb < 2; mb++) {
#pragma unroll
        for (int nb = 0; nb < 8; nb++) {
            int m = m0 + wm + mb * 16 + g;
            int n = n0 + wn + nb * 8 + tig * 2;
            size_t off0 = ((size_t)b * 512 + m) * HW + n;
            size_t off1 = off0 + (size_t)8 * HW;
            float* p = acc[mb][nb];
            *(__half2*)(Yh + off0) = __floats2half2_rn(p[0], p[1]);
            *(__half2*)(Yh + off1) = __floats2half2_rn(p[2], p[3]);
        }
    }
}

// ======== out-proj GEMM: Y = gamma*(W@X) + addend(fp16), fp32 out, M=512 ========
__global__ void __launch_bounds__(256, 2)
out_gemm_kernel(const __half* __restrict__ W, const __half* __restrict__ X,
                float* __restrict__ Y, const float* __restrict__ gammap,
                const __half* __restrict__ addend) {
    extern __shared__ __half sm[];
    uint32_t sbase = smem_u32(sm);
    int tid = threadIdx.x;
    int lane = tid & 31, wid = tid >> 5;
    int b = blockIdx.z;
    int m0 = blockIdx.y * 128, n0 = blockIdx.x * 128;
    const __half* wsrc = W + (size_t)m0 * 512;
    const __half* xsrc = X + (size_t)b * DIMC * HW + n0;

    auto copy_chunk = [&](int c) {
        uint32_t sb = sbase + (uint32_t)(c % 3) * (ST_ELEMS * 2);
#pragma unroll
        for (int i = 0; i < 4; i++) {
            int t = tid + i * 256;
            int m = t >> 3, j = t & 7;
            cp16(sb + (uint32_t)(m * A_PAD + j * 8) * 2,
                 wsrc + (size_t)m * 512 + c * 64 + j * 8);
        }
#pragma unroll
        for (int i = 0; i < 4; i++) {
            int t = tid + i * 256;
            int k = t >> 4, j = t & 15;
            cp16(sb + (uint32_t)(A_PL + k * B_PAD + j * 8) * 2,
                 xsrc + (size_t)(c * 64 + k) * HW + j * 8);
        }
        asm volatile("cp.async.commit_group;" ::: "memory");
    };

    float acc[2][8][4] = {};
    int wm = (wid & 3) * 32;
    int wn = (wid >> 2) * 64;

    GEMM_MAINLOOP(copy_chunk)

    float ga = gammap[0];
    int g = lane >> 2, tig = lane & 3;
#pragma unroll
    for (int mb = 0; mb < 2; mb++) {
#pragma unroll
        for (int nb = 0; nb < 8; nb++) {
            int m = m0 + wm + mb * 16 + g;
            int n = n0 + wn + nb * 8 + tig * 2;
            size_t off0 = ((size_t)b * 512 + m) * HW + n;
            size_t off1 = off0 + (size_t)8 * HW;
            float* p = acc[mb][nb];
            float2 d0 = __half22float2(*(const __half2*)(addend + off0));
            float2 d1 = __half22float2(*(const __half2*)(addend + off1));
            *(float2*)(Y + off0) = make_float2(ga * p[0] + d0.x, ga * p[1] + d0.y);
            *(float2*)(Y + off1) = make_float2(ga * p[2] + d1.x, ga * p[3] + d1.y);
        }
    }
}

// ======== v-gather GEMM: per bh, V[j][d] = sum_c wv[d,c]*ctx[c,p_j] (R11 form) ========
#define VG_APAD 520
#define VG_BOFF (64 * VG_APAD)
#define VG_SMEM ((VG_BOFF + 512 * 72) * 2)
__global__ void __launch_bounds__(128) vgather_kernel() {
    extern __shared__ __half sm[];
    __shared__ int sidx[16];
    uint32_t sbase = smem_u32(sm);
    int tid = threadIdx.x, lane = tid & 31, w = tid >> 5;
    int bh = blockIdx.x;

    if (tid < 8) sidx[tid] = g_idxh[bh * 8 + tid];
    else if (tid < 16) sidx[tid] = g_idxw[bh * 8 + tid - 8];

    const __half* wv = g_wkv + (size_t)(512 + (bh & 7) * 64) * 512;
#pragma unroll
    for (int i = 0; i < 32; i++) {
        int t = tid + i * 128;
        int row = t >> 6, j8 = t & 63;
        cp16(sbase + (uint32_t)(row * VG_APAD + j8 * 8) * 2, wv + row * 512 + j8 * 8);
    }
    asm volatile("cp.async.commit_group;" ::: "memory");
    __syncthreads();

    const __half* ctx = g_ctxh + (size_t)(bh >> 3) * DIMC * HW;
    int pj = sidx[(tid & 63) >> 3] * 64 + sidx[8 + (tid & 7)];
#pragma unroll 8
    for (int i = 0; i < 256; i++) {
        int t = tid + i * 128;
        int k = t >> 6, j = t & 63;
        sm[VG_BOFF + k * 72 + j] = ctx[(size_t)k * HW + pj];
    }
    asm volatile("cp.async.wait_group 0;" ::: "memory");
    __syncthreads();

    float acc[8][4] = {};
    uint32_t a_0 = sbase + (uint32_t)((w * 16 + (lane & 15)) * VG_APAD + (lane >> 4) * 8) * 2;
    uint32_t b_0 = sbase + (uint32_t)(VG_BOFF + (lane & 15) * 72 + (lane >> 4) * 8) * 2;
#pragma unroll 4
    for (int kc = 0; kc < 32; kc++) {
        uint32_t af[4], bf[4][4];
        ldsm4(af, a_0 + (uint32_t)(kc * 16) * 2);
#pragma unroll
        for (int nt2 = 0; nt2 < 4; nt2++)
            ldsm4t(bf[nt2], b_0 + (uint32_t)(kc * 16 * 72 + nt2 * 16) * 2);
#pragma unroll
        for (int nb = 0; nb < 8; nb++)
            mma16816(acc[nb], af, &bf[nb >> 1][(nb & 1) * 2]);
    }

    __half* dst = g_vf + bh * 4096;
    int g = lane >> 2, tig = lane & 3;
    int d0 = w * 16 + g;
#pragma unroll
    for (int nb = 0; nb < 8; nb++) {
        int j0 = nb * 8 + tig * 2;
        float* p = acc[nb];
        dst[j0 * 64 + d0]           = __float2half_rn(p[0]);
        dst[(j0 + 1) * 64 + d0]     = __float2half_rn(p[1]);
        dst[j0 * 64 + d0 + 8]       = __float2half_rn(p[2]);
        dst[(j0 + 1) * 64 + d0 + 8] = __float2half_rn(p[3]);
    }
}

// ---------------- fused channel layernorm (both tensors) + weight conversion ----------------
__global__ __launch_bounds__(256) void fused_norm_kernel(const float* __restrict__ in0,
                                                         const float* __restrict__ gw0,
                                                         const float* __restrict__ bw0,
                                                         __half* __restrict__ oh0,
                                                         const float* __restrict__ in1,
                                                         const float* __restrict__ gw1,
                                                         const float* __restrict__ bw1,
                                                         __half* __restrict__ oh1,
                                                         const float* __restrict__ wq,
                                                         const float* __restrict__ wkv,
                                                         const float* __restrict__ wo) {
    if (blockIdx.x >= 2048) {
        int i4 = ((blockIdx.x - 2048) * 256 + threadIdx.x) * 4;
        const float* src;
        __half* dst;
        int off;
        if (i4 < 262144)       { src = wq;  dst = g_wq;  off = i4; }
        else if (i4 < 786432)  { src = wkv; dst = g_wkv; off = i4 - 262144; }
        else                   { src = wo;  dst = g_wo;  off = i4 - 786432; }
        float4 x = *(const float4*)(src + off);
        *(__half2*)(dst + off)     = __floats2half2_rn(x.x, x.y);
        *(__half2*)(dst + off + 2) = __floats2half2_rn(x.z, x.w);
        return;
    }
    __shared__ float shs[8][32], shq[8][32];
    __shared__ float smean[32], srstd[32];
    int half2nd = blockIdx.x >> 10;
    const float* in = half2nd ? in1 : in0;
    const float* gw = half2nd ? gw1 : gw0;
    const float* bw = half2nd ? bw1 : bw0;
    __half* oh = half2nd ? oh1 : oh0;
    int tid = threadIdx.x;
    int px = tid & 31, cg = tid >> 5;
    int pos = (blockIdx.x & 1023) * 32 + px;
    int b = pos >> 12, sp = pos & 4095;
    size_t base = (size_t)b * DIMC * HW + sp;
    int c0 = cg * 64;
    float v[64];
    float s = 0.f, q = 0.f;
#pragma unroll 8
    for (int c = 0; c < 64; c++) {
        float x = in[base + (size_t)(c0 + c) * HW];
        v[c] = x; s += x; q += x * x;
    }
    shs[cg][px] = s; shq[cg][px] = q;
    __syncthreads();
    if (cg == 0) {
        float ts = 0.f, tq = 0.f;
#pragma unroll
        for (int g = 0; g < 8; g++) { ts += shs[g][px]; tq += shq[g][px]; }
        float mean = ts * (1.0f / 512.0f);
        float var = tq * (1.0f / 512.0f) - mean * mean;
        smean[px] = mean;
        srstd[px] = rsqrtf(var + 1e-5f);
    }
    __syncthreads();
    float m = smean[px], r = srstd[px];
#pragma unroll 8
    for (int c = 0; c < 64; c++) {
        float y = (v[c] - m) * r * gw[c0 + c] + bw[c0 + c];
        oh[base + (size_t)(c0 + c) * HW] = __float2half_rn(y);
    }
}

// ---------------- inverse L2 norms for q and k (half2, 2 positions/thread) ----------------
__global__ __launch_bounds__(256) void inv_norm_kernel() {
    int gidx = blockIdx.x * 256 + threadIdx.x;
    int qk = gidx >> 17;
    int id2 = gidx & 131071;
    int g = id2 >> 11, p2 = id2 & 2047;
    const __half* t = qk ? g_kk : g_qh;
    size_t base = (size_t)g * (64 * HW) + 2 * p2;
    float sx = 0.f, sy = 0.f;
#pragma unroll 8
    for (int d = 0; d < 64; d++) {
        float2 x = __half22float2(*(const __half2*)(t + base + (size_t)d * HW));
        sx += x.x * x.x;
        sy += x.y * x.y;
    }
    float2 r = make_float2(1.0f / fmaxf(sqrtf(sx), 1e-12f),
                           1.0f / fmaxf(sqrtf(sy), 1e-12f));
    float* dst = qk ? g_kinv : g_qinv;
    *(float2*)(dst + g * HW + 2 * p2) = r;
}

// ---------------- merged stats: khw (blocks 0..4095, register+shfl) + qprobe ----------------
__global__ __launch_bounds__(256) void stats_kernel() {
    int tid = threadIdx.x;
    int lane = tid & 31, wid = tid >> 5;
    if (blockIdx.x < 4096) {
        __shared__ float sc[8][64];
        int bh = blockIdx.x >> 6, c = blockIdx.x & 63;
        const __half2* kp2 = (const __half2*)(g_kk + ((size_t)bh * 64 + c) * HW);
        const float2* ki2 = (const float2*)(g_kinv + bh * HW);
        // thread covers columns {2*lane, 2*lane+1}, rows h = wid + 8j
        float csum0 = 0.f, csum1 = 0.f;
        float rsum[8];
#pragma unroll
        for (int j = 0; j < 8; j++) {
            int i = tid + 256 * j;
            float2 v = __half22float2(kp2[i]);
            float2 iv = ki2[i];
            float a0 = fabsf(v.x) * iv.x;
            float a1 = fabsf(v.y) * iv.y;
            csum0 += a0;
            csum1 += a1;
            rsum[j] = a0 + a1;
        }
        // row sums: reduce across the 32 lanes of this warp (each warp owns h = wid+8j)
#pragma unroll
        for (int st = 16; st > 0; st >>= 1) {
#pragma unroll
            for (int j = 0; j < 8; j++)
                rsum[j] += __shfl_xor_sync(0xffffffff, rsum[j], st);
        }
        if (lane < 8)
            g_kh[bh * 4096 + c * 64 + wid + 8 * lane] = rsum[lane];
        // column sums: combine 8 warps per column via small smem tile
        sc[wid][2 * lane]     = csum0;
        sc[wid][2 * lane + 1] = csum1;
        __syncthreads();
        if (tid < 64) {
            float s = 0.f;
#pragma unroll
            for (int g2 = 0; g2 < 8; g2++) s += sc[g2][tid];
            g_kw[bh * 4096 + c * 64 + tid] = s;
        }
    } else {
        __shared__ float ws[8];
        int bid = blockIdx.x - 4096;
        int g = bid >> 6;
        const __half2* p2 = (const __half2*)(g_qh + (size_t)bid * HW);
        const float2* iv2 = (const float2*)(g_qinv + (size_t)g * HW);
        float s = 0.f;
#pragma unroll 4
        for (int i = tid; i < 2048; i += 256) {
            float2 v = __half22float2(p2[i]);
            float2 iv = iv2[i];
            s += fabsf(v.x) * iv.x + fabsf(v.y) * iv.y;
        }
#pragma unroll
        for (int st = 16; st > 0; st >>= 1)
            s += __shfl_xor_sync(0xffffffff, s, st);
        if (lane == 0) ws[wid] = s;
        __syncthreads();
        if (tid == 0) {
            float t = 0.f;
#pragma unroll
            for (int g2 = 0; g2 < 8; g2++) t += ws[g2];
            g_qprobe[bid] = t;
        }
    }
}

// ---------------- scores + top-8 selection ----------------
__global__ __launch_bounds__(64) void score_topk_kernel() {
    int bh = blockIdx.x;
    int h = threadIdx.x;
    __shared__ float sr[64], sc[64];
    float a = 0.f, bb = 0.f;
    for (int c = 0; c < 64; c++) {
        float qp = g_qprobe[bh * 64 + c];
        a  += qp * g_kh[bh * 4096 + c * 64 + h];
        bb += qp * g_kw[bh * 4096 + c * 64 + h];
    }
    sr[h] = a; sc[h] = bb;
    __syncthreads();
    if (h == 0) {
        for (int i = 0; i < 8; i++) {
            float best = -INFINITY; int bi = 0;
            for (int j = 0; j < 64; j++) if (sr[j] > best) { best = sr[j]; bi = j; }
            g_idxh[bh * 8 + i] = bi;
            sr[bi] = -INFINITY;
        }
    } else if (h == 1) {
        for (int i = 0; i < 8; i++) {
            float best = -INFINITY; int bi = 0;
            for (int j = 0; j < 64; j++) if (sc[j] > best) { best = sc[j]; bi = j; }
            g_idxw[bh * 8 + i] = bi;
            sc[bi] = -INFINITY;
        }
    }
}

// ---------------- gather pruned k -> kT fp16 tile (R11 form) ----------------
__global__ __launch_bounds__(256) void gather_kernel() {
    int idx = blockIdx.x * 256 + threadIdx.x;   // 262144
    int bh = idx >> 12, r = (idx >> 6) & 63, cc = idx & 63;
    int hh = g_idxh[bh * 8 + (cc >> 3)];
    int ww = g_idxw[bh * 8 + (cc & 7)];
    int p = hh * 64 + ww;
    float k = __half2float(g_kk[((size_t)bh * 64 + r) * HW + p]) * g_kinv[bh * HW + p];
    g_kT[idx] = __float2half_rn(k);
}

// ---------------- MMA attention: per (bh, 128-query tile) (R11 form) ----------------
__global__ __launch_bounds__(128) void attn_kernel() {
    __shared__ __half sQ[128 * A_PAD];
    __shared__ __half sK[64 * A_PAD];
    __shared__ __half sV[64 * A_PAD];
    int tid = threadIdx.x, lane = tid & 31, w = tid >> 5;
    int p0 = blockIdx.x * 128, bh = blockIdx.y;
    uint32_t sQa = smem_u32(sQ), sKa = smem_u32(sK), sVa = smem_u32(sV);

    const __half* kt = g_kT + bh * 4096;
    const __half* vf = g_vf + bh * 4096;
#pragma unroll
    for (int i = 0; i < 4; i++) {
        int t = tid + i * 128;
        int r = t >> 3, j = t & 7;
        cp16(sKa + (uint32_t)(r * A_PAD + j * 8) * 2, kt + r * 64 + j * 8);
        cp16(sVa + (uint32_t)(r * A_PAD + j * 8) * 2, vf + r * 64 + j * 8);
    }
    asm volatile("cp.async.commit_group;" ::: "memory");

    const __half* qp = g_qh + (size_t)bh * 64 * HW + p0;
    const float* qi = g_qinv + bh * HW + p0;
#pragma unroll
    for (int i = 0; i < 32; i++) {
        int t = tid + i * 128;
        int d2 = t >> 7, p = t & 127;
        float iv = qi[p];
        __half2 h = __floats2half2_rn(__half2float(qp[(size_t)(2 * d2) * HW + p]) * iv,
                                      __half2float(qp[(size_t)(2 * d2 + 1) * HW + p]) * iv);
        *(__half2*)(sQ + p * A_PAD + 2 * d2) = h;
    }
    asm volatile("cp.async.wait_group 0;" ::: "memory");
    __syncthreads();

    float sacc[2][8][4] = {};
#pragma unroll
    for (int kk = 0; kk < 4; kk++) {
        uint32_t a[2][4], bk[4][4];
#pragma unroll
        for (int mb = 0; mb < 2; mb++)
            ldsm4(a[mb], sQa + (uint32_t)((w * 32 + mb * 16 + (lane & 15)) * A_PAD
                                          + kk * 16 + (lane >> 4) * 8) * 2);
#pragma unroll
        for (int nt2 = 0; nt2 < 4; nt2++)
            ldsm4t(bk[nt2], sKa + (uint32_t)((kk * 16 + (lane & 15)) * A_PAD
                                             + nt2 * 16 + (lane >> 4) * 8) * 2);
#pragma unroll
        for (int mb = 0; mb < 2; mb++)
#pragma unroll
            for (int nt = 0; nt < 8; nt++)
                mma16816(sacc[mb][nt], a[mb], &bk[nt >> 1][(nt & 1) * 2]);
    }

    float is0[2], is1[2];
#pragma unroll
    for (int mb = 0; mb < 2; mb++) {
        float mx0 = -INFINITY, mx1 = -INFINITY;
#pragma unroll
        for (int nt = 0; nt < 8; nt++) {
            mx0 = fmaxf(mx0, fmaxf(sacc[mb][nt][0], sacc[mb][nt][1]));
            mx1 = fmaxf(mx1, fmaxf(sacc[mb][nt][2], sacc[mb][nt][3]));
        }
        mx0 = fmaxf(mx0, __shfl_xor_sync(0xffffffff, mx0, 1));
        mx0 = fmaxf(mx0, __shfl_xor_sync(0xffffffff, mx0, 2));
        mx1 = fmaxf(mx1, __shfl_xor_sync(0xffffffff, mx1, 1));
        mx1 = fmaxf(mx1, __shfl_xor_sync(0xffffffff, mx1, 2));
        float s0 = 0.f, s1 = 0.f;
#pragma unroll
        for (int nt = 0; nt < 8; nt++) {
            sacc[mb][nt][0] = expf(sacc[mb][nt][0] - mx0);
            sacc[mb][nt][1] = expf(sacc[mb][nt][1] - mx0);
            sacc[mb][nt][2] = expf(sacc[mb][nt][2] - mx1);
            sacc[mb][nt][3] = expf(sacc[mb][nt][3] - mx1);
            s0 += sacc[mb][nt][0] + sacc[mb][nt][1];
            s1 += sacc[mb][nt][2] + sacc[mb][nt][3];
        }
        s0 += __shfl_xor_sync(0xffffffff, s0, 1);
        s0 += __shfl_xor_sync(0xffffffff, s0, 2);
        s1 += __shfl_xor_sync(0xffffffff, s1, 1);
        s1 += __shfl_xor_sync(0xffffffff, s1, 2);
        is0[mb] = 1.0f / s0;
        is1[mb] = 1.0f / s1;
    }

    uint32_t pa[2][4][4];
#pragma unroll
    for (int mb = 0; mb < 2; mb++)
#pragma unroll
        for (int u = 0; u < 4; u++) {
            __half2 h0 = __floats2half2_rn(sacc[mb][2*u][0],   sacc[mb][2*u][1]);
            __half2 h1 = __floats2half2_rn(sacc[mb][2*u][2],   sacc[mb][2*u][3]);
            __half2 h2 = __floats2half2_rn(sacc[mb][2*u+1][0], sacc[mb][2*u+1][1]);
            __half2 h3 = __floats2half2_rn(sacc[mb][2*u+1][2], sacc[mb][2*u+1][3]);
            pa[mb][u][0] = *(uint32_t*)&h0;
            pa[mb][u][1] = *(uint32_t*)&h1;
            pa[mb][u][2] = *(uint32_t*)&h2;
            pa[mb][u][3] = *(uint32_t*)&h3;
        }

    float oacc[2][8][4] = {};
#pragma unroll
    for (int u = 0; u < 4; u++) {
        uint32_t bv[4][4];
#pragma unroll
        for (int nt2 = 0; nt2 < 4; nt2++)
            ldsm4t(bv[nt2], sVa + (uint32_t)((u * 16 + (lane & 15)) * A_PAD
                                             + nt2 * 16 + (lane >> 4) * 8) * 2);
#pragma unroll
        for (int mb = 0; mb < 2; mb++)
#pragma unroll
            for (int nt = 0; nt < 8; nt++)
                mma16816(oacc[mb][nt], pa[mb][u], &bv[nt >> 1][(nt & 1) * 2]);
    }

    __syncthreads();
#pragma unroll
    for (int mb = 0; mb < 2; mb++) {
        int q = w * 32 + mb * 16 + (lane >> 2);
#pragma unroll
        for (int nt = 0; nt < 8; nt++) {
            int d = nt * 8 + (lane & 3) * 2;
            __half2 h0 = __floats2half2_rn(oacc[mb][nt][0] * is0[mb],
                                           oacc[mb][nt][1] * is0[mb]);
            __half2 h1 = __floats2half2_rn(oacc[mb][nt][2] * is1[mb],
                                           oacc[mb][nt][3] * is1[mb]);
            *(__half2*)(sQ + q * A_PAD + d) = h0;
            *(__half2*)(sQ + (q + 8) * A_PAD + d) = h1;
        }
    }
    __syncthreads();

    size_t ob = ((size_t)(bh >> 3) * 512 + (size_t)(bh & 7) * 64) * HW + p0;
    for (int i = tid; i < 4096; i += 128) {
        int d = i >> 6, jj = i & 63;
        __half2 h = __halves2half2(sQ[(jj * 2) * A_PAD + d],
                                   sQ[(jj * 2 + 1) * A_PAD + d]);
        *(__half2*)(g_aoh + ob + (size_t)d * HW + jj * 2) = h;
    }
}

// ---------------- launch ----------------
extern "C" void kernel_launch(void* const* d_in, const int* in_sizes, int n_in,
                              void* d_out, int out_size) {
    (void)in_sizes; (void)n_in; (void)out_size;
    const float* context      = (const float*)d_in[0];
    const float* query_source = (const float*)d_in[1];
    const float* ctx_g = (const float*)d_in[2];
    const float* ctx_b = (const float*)d_in[3];
    const float* qs_g  = (const float*)d_in[4];
    const float* qs_b  = (const float*)d_in[5];
    const float* w_q   = (const float*)d_in[6];
    const float* w_kv  = (const float*)d_in[7];
    const float* w_out = (const float*)d_in[8];
    const float* gamma = (const float*)d_in[9];
    float* out = (float*)d_out;

    static bool inited = false;
    static __half *p_qh, *p_kk, *p_ctxh, *p_qsh, *p_aoh, *p_wq, *p_wkv, *p_wo;
    if (!inited) {
        cudaGetSymbolAddress((void**)&p_qh,   g_qh);
        cudaGetSymbolAddress((void**)&p_kk,   g_kk);
        cudaGetSymbolAddress((void**)&p_ctxh, g_ctxh);
        cudaGetSymbolAddress((void**)&p_qsh,  g_qsh);
        cudaGetSymbolAddress((void**)&p_aoh,  g_aoh);
        cudaGetSymbolAddress((void**)&p_wq,   g_wq);
        cudaGetSymbolAddress((void**)&p_wkv,  g_wkv);
        cudaGetSymbolAddress((void**)&p_wo,   g_wo);
        cudaFuncSetAttribute(proj_gemm_kernel,
                             cudaFuncAttributeMaxDynamicSharedMemorySize, GEMM_SMEM);
        cudaFuncSetAttribute(out_gemm_kernel,
                             cudaFuncAttributeMaxDynamicSharedMemorySize, GEMM_SMEM);
        cudaFuncSetAttribute(vgather_kernel,
                             cudaFuncAttributeMaxDynamicSharedMemorySize, VG_SMEM);
        inited = true;
    }

    // 1) fused channel layernorms + weight conversion (one launch)
    fused_norm_kernel<<<3072, 256>>>(context, ctx_g, ctx_b, p_ctxh,
                                     query_source, qs_g, qs_b, p_qsh,
                                     w_q, w_kv, w_out);

    // 2) merged k + q projections
    proj_gemm_kernel<<<dim3(32, 4, 16), 256, GEMM_SMEM>>>(p_wkv, p_ctxh, p_kk,
                                                          p_wq, p_qsh, p_qh);

    // 3) inverse L2 norms (half2)
    inv_norm_kernel<<<1024, 256>>>();

    // 4) pruning statistics + selection
    stats_kernel<<<8192, 256>>>();
    score_topk_kernel<<<64, 64>>>();

    // 5) gather k^T; compute V only at gathered positions
    gather_kernel<<<1024, 256>>>();
    vgather_kernel<<<64, 128, VG_SMEM>>>();

    // 6) MMA attention
    attn_kernel<<<dim3(32, 64), 128>>>();

    // 7) out projection + fp16 residual
    out_gemm_kernel<<<dim3(32, 4, 8), 256, GEMM_SMEM>>>(p_wo, p_aoh, out, gamma, p_qsh);
}